// round 8
// baseline (speedup 1.0000x reference)
#include <cuda_runtime.h>
#include <cuda_fp16.h>
#include <mma.h>
#include <math.h>
#include <stdint.h>

using namespace nvcuda;

// Problem constants
#define NB    256
#define VN    7
#define CT    16384
#define CTV   114688      // CT*VN
#define EOUT  256
#define NV    1792        // NB*VN
#define ALPHA 0.2f

// GEMM tiling
#define KSPLIT  8
#define KSLICE  2048      // CT/KSPLIT
#define BM      128
#define BN      256
#define BK      32
#define NST     (KSLICE / BK)   // 64 stages
#define SA      40               // smem row stride in halves (80B = 5x16B)
#define ABUFH   (BM * SA)        // 5120 halves
#define BBUFH   (BN * SA)        // 10240 halves

// Scratch
__device__ __half g_Wth[EOUT * CT];            // 8 MB  W^T hi
__device__ __half g_Wtl[EOUT * CT];            // 8 MB  W^T lo
__device__ float  g_Whp[KSPLIT * NV * EOUT];   // 14.7 MB split-K partials

__device__ __forceinline__ uint32_t smem_u32(const void* p) {
    uint32_t a;
    asm("{ .reg .u64 t; cvta.to.shared.u64 t, %1; cvt.u32.u64 %0, t; }" : "=r"(a) : "l"(p));
    return a;
}
#define CP_ASYNC16(dst, src) \
    asm volatile("cp.async.cg.shared.global [%0], [%1], 16;" :: "r"(dst), "l"(src))
#define CP_COMMIT() asm volatile("cp.async.commit_group;")
#define CP_WAIT0()  asm volatile("cp.async.wait_group 0;")

// ---------------------------------------------------------------------------
// W transpose + fp16 hi/lo split
// ---------------------------------------------------------------------------
__global__ __launch_bounds__(256) void transpose_W(const float* __restrict__ W) {
    __shared__ float tile[32][33];
    const int k0 = blockIdx.x * 32, o0 = blockIdx.y * 32;
    const int tx = threadIdx.x & 31, ty = threadIdx.x >> 5;
#pragma unroll
    for (int r = 0; r < 32; r += 8)
        tile[ty + r][tx] = W[(size_t)(k0 + ty + r) * EOUT + o0 + tx];
    __syncthreads();
#pragma unroll
    for (int r = 0; r < 32; r += 8) {
        const float x = tile[tx][ty + r];
        const __half hx = __float2half_rn(x);
        const __half lx = __float2half_rn(x - __half2float(hx));
        const size_t idx = (size_t)(o0 + ty + r) * CT + k0 + tx;
        g_Wth[idx] = hx;
        g_Wtl[idx] = lx;
    }
}

// ---------------------------------------------------------------------------
// fp16x3 GEMM via wmma, split-K. Grid (14, 1, 8), 512 threads (16 warps).
// A loaded as coalesced float4 over the contiguous per-n footprint, scattered
// into padded SMEM via precomputed k-invariant destinations.
// ---------------------------------------------------------------------------
__global__ __launch_bounds__(512, 1) void gemm_mma(const float* __restrict__ h) {
    extern __shared__ __half smh[];
    __half* const AHb = smh;                       // 2 stages ABUFH
    __half* const ALb = smh + 2 * ABUFH;
    __half* const BHb = smh + 4 * ABUFH;           // 2 stages BBUFH
    __half* const BLb = smh + 4 * ABUFH + 2 * BBUFH;

    const int tid = threadIdx.x, wid = tid >> 5;
    const int m0 = blockIdx.x * BM, ks = blockIdx.z;
    const int kbase = ks * KSLICE;

    // ---- A coalesced-gather geometry ----
    // footprint: n in [n_lo, n_hi], per n 224 contiguous floats starting at
    // n*CTV + k0*7. float4 index: (n_lo+nr)*28672 + fr + k0*7/4.
    const int r7   = m0 % 7;
    const int n_lo = m0 / 7;
    const int nn   = (r7 + 127) / 7 + 1;   // 19 or 20
    const int nf4  = nn * 56;
    int src4[3];
    int dstE[3][4];
#pragma unroll
    for (int t = 0; t < 3; t++) {
        const int f = tid + t * 512;
        if (f < nf4) {
            const int nr = f / 56, fr = f - nr * 56;
            src4[t] = (n_lo + nr) * (CTV / 4) + fr;
#pragma unroll
            for (int i = 0; i < 4; i++) {
                const int rem = fr * 4 + i;
                const int kk = rem / 7, v = rem - 7 * kk;
                const int row = nr * 7 + v - r7;
                dstE[t][i] = (row >= 0 && row < BM) ? (row * SA + kk) : -1;
            }
        } else {
            src4[t] = -1;
        }
    }
    const float4* const h4 = reinterpret_cast<const float4*>(h);
    const int koff0 = ks * 3584;   // kbase*7/4

    // ---- B cp.async geometry ----
    const uint32_t sm_base = smem_u32(smh);
    int bsrc[2];
    uint32_t bdstoff[2];
#pragma unroll
    for (int r = 0; r < 2; r++) {
        const int j = r * 512 + tid;
        const int o = j >> 2, kq = j & 3;
        bsrc[r] = o * CT + kq * 8;
        bdstoff[r] = (uint32_t)(o * SA + kq * 8) * 2;
    }

    wmma::fragment<wmma::accumulator, 16, 16, 16, float> acc[4][2];
#pragma unroll
    for (int mf = 0; mf < 4; mf++)
#pragma unroll
        for (int nf = 0; nf < 2; nf++) wmma::fill_fragment(acc[mf][nf], 0.f);

    const int mw = (wid >> 3) * 64;
    const int nw = (wid & 7) * 32;

    // helper lambda-ish macros via plain code
    float4 aR[3];

    // ---- prologue: stage 0 ----
    {
#pragma unroll
        for (int t = 0; t < 3; t++)
            if (src4[t] >= 0) aR[t] = h4[(size_t)src4[t] + koff0];
        const uint32_t bh0 = sm_base + (4 * ABUFH) * 2;
        const uint32_t bl0 = sm_base + (4 * ABUFH + 2 * BBUFH) * 2;
#pragma unroll
        for (int r = 0; r < 2; r++) {
            CP_ASYNC16(bh0 + bdstoff[r], (const char*)&g_Wth[(size_t)bsrc[r] + kbase]);
            CP_ASYNC16(bl0 + bdstoff[r], (const char*)&g_Wtl[(size_t)bsrc[r] + kbase]);
        }
        CP_COMMIT();
        __half* const ah = AHb;
        __half* const al = ALb;
#pragma unroll
        for (int t = 0; t < 3; t++) {
            if (src4[t] >= 0) {
                const float xs[4] = {aR[t].x, aR[t].y, aR[t].z, aR[t].w};
#pragma unroll
                for (int i = 0; i < 4; i++) {
                    const int d = dstE[t][i];
                    if (d >= 0) {
                        const __half hx = __float2half_rn(xs[i]);
                        ah[d] = hx;
                        al[d] = __float2half_rn(xs[i] - __half2float(hx));
                    }
                }
            }
        }
        CP_WAIT0();
        __syncthreads();
    }

#pragma unroll 1
    for (int s = 0; s < NST; s++) {
        const int buf = s & 1;
        const int nxt = buf ^ 1;
        __half* const ah = AHb + buf * ABUFH;
        __half* const al = ALb + buf * ABUFH;
        __half* const bh = BHb + buf * BBUFH;
        __half* const bl = BLb + buf * BBUFH;

        const bool more = (s + 1 < NST);
        if (more) {
            const int koff = koff0 + (s + 1) * 56;
#pragma unroll
            for (int t = 0; t < 3; t++)
                if (src4[t] >= 0) aR[t] = h4[(size_t)src4[t] + koff];
            const int kn = kbase + (s + 1) * BK;
            const uint32_t bhn = sm_base + (4 * ABUFH + nxt * BBUFH) * 2;
            const uint32_t bln = sm_base + (4 * ABUFH + (2 + nxt) * BBUFH) * 2;
#pragma unroll
            for (int r = 0; r < 2; r++) {
                CP_ASYNC16(bhn + bdstoff[r], (const char*)&g_Wth[(size_t)bsrc[r] + kn]);
                CP_ASYNC16(bln + bdstoff[r], (const char*)&g_Wtl[(size_t)bsrc[r] + kn]);
            }
        }
        CP_COMMIT();

        // compute stage s
#pragma unroll
        for (int c = 0; c < 2; c++) {
            const int kk = c * 16;
            wmma::fragment<wmma::matrix_a, 16, 16, 16, __half, wmma::row_major> aH[4], aL[4];
#pragma unroll
            for (int mf = 0; mf < 4; mf++) {
                wmma::load_matrix_sync(aH[mf], ah + (mw + mf * 16) * SA + kk, SA);
                wmma::load_matrix_sync(aL[mf], al + (mw + mf * 16) * SA + kk, SA);
            }
            wmma::fragment<wmma::matrix_b, 16, 16, 16, __half, wmma::col_major> bH[2], bL[2];
#pragma unroll
            for (int nf = 0; nf < 2; nf++) {
                wmma::load_matrix_sync(bH[nf], bh + (nw + nf * 16) * SA + kk, SA);
                wmma::load_matrix_sync(bL[nf], bl + (nw + nf * 16) * SA + kk, SA);
            }
#pragma unroll
            for (int mf = 0; mf < 4; mf++)
#pragma unroll
                for (int nf = 0; nf < 2; nf++) {
                    wmma::mma_sync(acc[mf][nf], aH[mf], bH[nf], acc[mf][nf]);
                    wmma::mma_sync(acc[mf][nf], aH[mf], bL[nf], acc[mf][nf]);
                    wmma::mma_sync(acc[mf][nf], aL[mf], bH[nf], acc[mf][nf]);
                }
        }

        // STS A for stage s+1
        if (more) {
            __half* const ahn = AHb + nxt * ABUFH;
            __half* const aln = ALb + nxt * ABUFH;
#pragma unroll
            for (int t = 0; t < 3; t++) {
                if (src4[t] >= 0) {
                    const float xs[4] = {aR[t].x, aR[t].y, aR[t].z, aR[t].w};
#pragma unroll
                    for (int i = 0; i < 4; i++) {
                        const int d = dstE[t][i];
                        if (d >= 0) {
                            const __half hx = __float2half_rn(xs[i]);
                            ahn[d] = hx;
                            aln[d] = __float2half_rn(xs[i] - __half2float(hx));
                        }
                    }
                }
            }
        }
        CP_WAIT0();
        __syncthreads();
    }

    // epilogue: store partials
#pragma unroll
    for (int mf = 0; mf < 4; mf++)
#pragma unroll
        for (int nf = 0; nf < 2; nf++) {
            float* dst = g_Whp + ((size_t)ks * NV + m0 + mw + mf * 16) * EOUT
                       + nw + nf * 16;
            wmma::store_matrix_sync(dst, acc[mf][nf], EOUT, wmma::mem_row_major);
        }
}

// ---------------------------------------------------------------------------
// Per-batch attention epilogue: fused split-K reduce + adj-norm + attention
// ---------------------------------------------------------------------------
__global__ __launch_bounds__(256) void attn_kernel(const float* __restrict__ a,
                                                   const float* __restrict__ Bp,
                                                   float* __restrict__ out) {
    const int n = blockIdx.x;
    const int t = threadIdx.x;

    __shared__ float Whs[VN][EOUT];   // 7 KB
    __shared__ float adj[49];
    __shared__ float amin, amax;
    __shared__ float dis[7];
    __shared__ float s1[8], s2[8];
    __shared__ float smx[7][7];
    __shared__ float att[7][7];

    // --- fused split-K reduction for this batch's 7 rows ---
#pragma unroll
    for (int v = 0; v < VN; v++) {
        const size_t base = (size_t)(n * VN + v) * EOUT + t;
        float acc = 0.f;
#pragma unroll
        for (int ks = 0; ks < KSPLIT; ks++)
            acc += g_Whp[(size_t)ks * (NV * EOUT) + base];
        Whs[v][t] = acc;
    }

    // --- adjacency normalization ---
    if (t < 49) {
        const int i = t / 7, j = t - (t / 7) * 7;
        adj[t] = Bp[t] + 1e-6f + (i == j ? 1.f : 0.f);
    }
    __syncthreads();
    if (t == 0) {
        float mn = adj[0], mx = adj[0];
        for (int s = 1; s < 49; s++) { mn = fminf(mn, adj[s]); mx = fmaxf(mx, adj[s]); }
        amin = mn; amax = mx;
    }
    __syncthreads();
    if (t < 49) adj[t] = (adj[t] - amin) / (amax - amin);
    __syncthreads();
    if (t < 7) {
        float s = 0.f;
        for (int j = 0; j < 7; j++) s += adj[t * 7 + j];
        dis[t] = 1.0f / sqrtf(s);
    }
    __syncthreads();
    if (t < 49) {
        const int i = t / 7, j = t - (t / 7) * 7;
        adj[t] = dis[i] * adj[t] * dis[j];
    }

    // --- s1/s2 dot products ---
    const int w = t >> 5, l = t & 31;
    if (w < 7) {
        float p1 = 0.f, p2 = 0.f;
#pragma unroll
        for (int o = l; o < EOUT; o += 32) {
            const float x = Whs[w][o];
            p1 += x * a[o];
            p2 += x * a[EOUT + o];
        }
#pragma unroll
        for (int off = 16; off > 0; off >>= 1) {
            p1 += __shfl_down_sync(0xffffffffu, p1, off);
            p2 += __shfl_down_sync(0xffffffffu, p2, off);
        }
        if (l == 0) { s1[w] = p1; s2[w] = p2; }
    }
    __syncthreads();

    if (t < 7) {
        float e[7];
        float mx = -1e30f;
#pragma unroll
        for (int u = 0; u < 7; u++) {
            float x = s1[t] + s2[u];
            x = (x > 0.f) ? x : ALPHA * x;
            e[u] = x;
            mx = fmaxf(mx, x);
        }
        float s = 0.f;
#pragma unroll
        for (int u = 0; u < 7; u++) { e[u] = expf(e[u] - mx); s += e[u]; }
        const float inv = 1.f / s;
#pragma unroll
        for (int u = 0; u < 7; u++) smx[t][u] = e[u] * inv;
    }
    __syncthreads();

    if (t < 49) {
        const int i = t / 7, j = t - (t / 7) * 7;
        float s = 0.f;
#pragma unroll
        for (int u = 0; u < 7; u++) s += adj[i * 7 + u] * smx[u][j];
        att[i][j] = s;
    }
    __syncthreads();

    float whu[7];
#pragma unroll
    for (int u = 0; u < 7; u++) whu[u] = Whs[u][t];

#pragma unroll
    for (int v = 0; v < 7; v++) {
        float hp = 0.f;
#pragma unroll
        for (int u = 0; u < 7; u++) hp = fmaf(att[v][u], whu[u], hp);
        const float r = (hp > 0.f) ? hp : expm1f(hp);
        out[n * (VN * EOUT) + v * EOUT + t] = r;
    }
}

// ---------------------------------------------------------------------------
extern "C" void kernel_launch(void* const* d_in, const int* in_sizes, int n_in,
                              void* d_out, int out_size) {
    const float* h  = (const float*)d_in[0];
    const float* W  = (const float*)d_in[1];
    const float* a  = (const float*)d_in[2];
    const float* Bp = (const float*)d_in[3];
    float* out = (float*)d_out;

    const int smem_bytes = (4 * ABUFH + 4 * BBUFH) * 2;   // 122880
    cudaFuncSetAttribute(gemm_mma, cudaFuncAttributeMaxDynamicSharedMemorySize, smem_bytes);

    transpose_W<<<dim3(CT / 32, EOUT / 32), 256>>>(W);
    gemm_mma<<<dim3(NV / BM, 1, KSPLIT), 512, smem_bytes>>>(h);
    attn_kernel<<<NB, 256>>>(a, Bp, out);
}

// round 9
// speedup vs baseline: 1.1740x; 1.1740x over previous
#include <cuda_runtime.h>
#include <cuda_fp16.h>
#include <mma.h>
#include <math.h>
#include <stdint.h>

using namespace nvcuda;

// Problem constants
#define NB    256
#define VN    7
#define CT    16384
#define CTV   114688      // CT*VN
#define EOUT  256
#define NV    1792        // NB*VN
#define ALPHA 0.2f

// GEMM tiling
#define BM      128
#define BN      256
#define BK      32
#define KU      512              // total BK-units (CT/BK)
#define KSMAX   11               // max splits per mtile
#define SA      40               // smem row stride in halves
#define ABUFH   (BM * SA)        // 5120 halves
#define BBUFH   (BN * SA)        // 10240 halves

// Scratch
__device__ __half g_Wth[EOUT * CT];              // 8 MB  W^T hi
__device__ __half g_Wtl[EOUT * CT];              // 8 MB  W^T lo
__device__ float  g_Whp[KSMAX * NV * EOUT];      // 20.2 MB split-K partials

__device__ __forceinline__ uint32_t smem_u32(const void* p) {
    uint32_t a;
    asm("{ .reg .u64 t; cvta.to.shared.u64 t, %1; cvt.u32.u64 %0, t; }" : "=r"(a) : "l"(p));
    return a;
}
#define CP_ASYNC16(dst, src) \
    asm volatile("cp.async.cg.shared.global [%0], [%1], 16;" :: "r"(dst), "l"(src))
#define CP_COMMIT() asm volatile("cp.async.commit_group;")
#define CP_WAIT0()  asm volatile("cp.async.wait_group 0;")

// ---------------------------------------------------------------------------
// W transpose + fp16 hi/lo split
// ---------------------------------------------------------------------------
__global__ __launch_bounds__(256) void transpose_W(const float* __restrict__ W) {
    __shared__ float tile[32][33];
    const int k0 = blockIdx.x * 32, o0 = blockIdx.y * 32;
    const int tx = threadIdx.x & 31, ty = threadIdx.x >> 5;
#pragma unroll
    for (int r = 0; r < 32; r += 8)
        tile[ty + r][tx] = W[(size_t)(k0 + ty + r) * EOUT + o0 + tx];
    __syncthreads();
#pragma unroll
    for (int r = 0; r < 32; r += 8) {
        const float x = tile[tx][ty + r];
        const __half hx = __float2half_rn(x);
        const __half lx = __float2half_rn(x - __half2float(hx));
        const size_t idx = (size_t)(o0 + ty + r) * CT + k0 + tx;
        g_Wth[idx] = hx;
        g_Wtl[idx] = lx;
    }
}

// ---------------------------------------------------------------------------
// Zero-fill unused partial slot 10 for mtiles 8..13 (rows 1024..1791)
// ---------------------------------------------------------------------------
__global__ __launch_bounds__(256) void zero_slot10() {
    const size_t base = (size_t)10 * NV * EOUT + 1024 * EOUT;   // floats
    float4* z = reinterpret_cast<float4*>(g_Whp + base);
    const int n4 = 768 * EOUT / 4;   // 49152
    for (int i = blockIdx.x * 256 + threadIdx.x; i < n4; i += gridDim.x * 256)
        z[i] = make_float4(0.f, 0.f, 0.f, 0.f);
}

// ---------------------------------------------------------------------------
// fp16x3 GEMM via wmma, uneven split-K over exactly 148 CTAs.
// mtiles 0..7: 11 splits (ctas 0..87); mtiles 8..13: 10 splits (ctas 88..147).
// ---------------------------------------------------------------------------
__global__ __launch_bounds__(512, 1) void gemm_mma(const float* __restrict__ h) {
    extern __shared__ __half smh[];
    __half* const AHb = smh;                       // 2 stages ABUFH
    __half* const ALb = smh + 2 * ABUFH;
    __half* const BHb = smh + 4 * ABUFH;           // 2 stages BBUFH
    __half* const BLb = smh + 4 * ABUFH + 2 * BBUFH;

    const int tid = threadIdx.x, wid = tid >> 5;
    const int cta = blockIdx.x;

    int mtile, split, nsplit;
    if (cta < 88) { mtile = cta / 11; split = cta - mtile * 11; nsplit = 11; }
    else { const int c2 = cta - 88; const int q = c2 / 10; mtile = 8 + q; split = c2 - q * 10; nsplit = 10; }
    const int m0 = mtile * BM;
    const int u0 = (KU * split) / nsplit;
    const int u1 = (KU * (split + 1)) / nsplit;
    const int nst = u1 - u0;           // 46..52 stages
    const int kbase = u0 * BK;

    // ---- A coalesced-gather geometry (contiguous per-n footprint) ----
    const int r7   = m0 % 7;
    const int n_lo = m0 / 7;
    const int nn   = (r7 + 127) / 7 + 1;
    const int nf4  = nn * 56;
    int src4[3];
    int dstE[3][4];
#pragma unroll
    for (int t = 0; t < 3; t++) {
        const int f = tid + t * 512;
        if (f < nf4) {
            const int nr = f / 56, fr = f - nr * 56;
            src4[t] = (n_lo + nr) * (CTV / 4) + fr;
#pragma unroll
            for (int i = 0; i < 4; i++) {
                const int rem = fr * 4 + i;
                const int kk = rem / 7, v = rem - 7 * kk;
                const int row = nr * 7 + v - r7;
                dstE[t][i] = (row >= 0 && row < BM) ? (row * SA + kk) : -1;
            }
        } else {
            src4[t] = -1;
        }
    }
    const float4* const h4 = reinterpret_cast<const float4*>(h);
    const int koff0 = u0 * 56;   // kbase*7/4

    // ---- B cp.async geometry ----
    const uint32_t sm_base = smem_u32(smh);
    int bsrc[2];
    uint32_t bdstoff[2];
#pragma unroll
    for (int r = 0; r < 2; r++) {
        const int j = r * 512 + tid;
        const int o = j >> 2, kq = j & 3;
        bsrc[r] = o * CT + kq * 8;
        bdstoff[r] = (uint32_t)(o * SA + kq * 8) * 2;
    }

    wmma::fragment<wmma::accumulator, 16, 16, 16, float> acc[4][2];
#pragma unroll
    for (int mf = 0; mf < 4; mf++)
#pragma unroll
        for (int nf = 0; nf < 2; nf++) wmma::fill_fragment(acc[mf][nf], 0.f);

    const int mw = (wid >> 3) * 64;
    const int nw = (wid & 7) * 32;

    float4 aR[3];

    // ---- prologue: stage 0 ----
    {
#pragma unroll
        for (int t = 0; t < 3; t++)
            if (src4[t] >= 0) aR[t] = h4[(size_t)src4[t] + koff0];
        const uint32_t bh0 = sm_base + (4 * ABUFH) * 2;
        const uint32_t bl0 = sm_base + (4 * ABUFH + 2 * BBUFH) * 2;
#pragma unroll
        for (int r = 0; r < 2; r++) {
            CP_ASYNC16(bh0 + bdstoff[r], (const char*)&g_Wth[(size_t)bsrc[r] + kbase]);
            CP_ASYNC16(bl0 + bdstoff[r], (const char*)&g_Wtl[(size_t)bsrc[r] + kbase]);
        }
        CP_COMMIT();
        __half* const ah = AHb;
        __half* const al = ALb;
#pragma unroll
        for (int t = 0; t < 3; t++) {
            if (src4[t] >= 0) {
                const float xs[4] = {aR[t].x, aR[t].y, aR[t].z, aR[t].w};
#pragma unroll
                for (int i = 0; i < 4; i++) {
                    const int d = dstE[t][i];
                    if (d >= 0) {
                        const __half hx = __float2half_rn(xs[i]);
                        ah[d] = hx;
                        al[d] = __float2half_rn(xs[i] - __half2float(hx));
                    }
                }
            }
        }
        CP_WAIT0();
        __syncthreads();
    }

#pragma unroll 1
    for (int s = 0; s < nst; s++) {
        const int buf = s & 1;
        const int nxt = buf ^ 1;
        __half* const ah = AHb + buf * ABUFH;
        __half* const al = ALb + buf * ABUFH;
        __half* const bh = BHb + buf * BBUFH;
        __half* const bl = BLb + buf * BBUFH;

        const bool more = (s + 1 < nst);
        if (more) {
            const int koff = koff0 + (s + 1) * 56;
#pragma unroll
            for (int t = 0; t < 3; t++)
                if (src4[t] >= 0) aR[t] = h4[(size_t)src4[t] + koff];
            const int kn = kbase + (s + 1) * BK;
            const uint32_t bhn = sm_base + (4 * ABUFH + nxt * BBUFH) * 2;
            const uint32_t bln = sm_base + (4 * ABUFH + (2 + nxt) * BBUFH) * 2;
#pragma unroll
            for (int r = 0; r < 2; r++) {
                CP_ASYNC16(bhn + bdstoff[r], (const char*)&g_Wth[(size_t)bsrc[r] + kn]);
                CP_ASYNC16(bln + bdstoff[r], (const char*)&g_Wtl[(size_t)bsrc[r] + kn]);
            }
        }
        CP_COMMIT();

        // compute stage s
#pragma unroll
        for (int c = 0; c < 2; c++) {
            const int kk = c * 16;
            wmma::fragment<wmma::matrix_a, 16, 16, 16, __half, wmma::row_major> aH[4], aL[4];
#pragma unroll
            for (int mf = 0; mf < 4; mf++) {
                wmma::load_matrix_sync(aH[mf], ah + (mw + mf * 16) * SA + kk, SA);
                wmma::load_matrix_sync(aL[mf], al + (mw + mf * 16) * SA + kk, SA);
            }
            wmma::fragment<wmma::matrix_b, 16, 16, 16, __half, wmma::col_major> bH[2], bL[2];
#pragma unroll
            for (int nf = 0; nf < 2; nf++) {
                wmma::load_matrix_sync(bH[nf], bh + (nw + nf * 16) * SA + kk, SA);
                wmma::load_matrix_sync(bL[nf], bl + (nw + nf * 16) * SA + kk, SA);
            }
#pragma unroll
            for (int mf = 0; mf < 4; mf++)
#pragma unroll
                for (int nf = 0; nf < 2; nf++) {
                    wmma::mma_sync(acc[mf][nf], aH[mf], bH[nf], acc[mf][nf]);
                    wmma::mma_sync(acc[mf][nf], aH[mf], bL[nf], acc[mf][nf]);
                    wmma::mma_sync(acc[mf][nf], aL[mf], bH[nf], acc[mf][nf]);
                }
        }

        // STS A for stage s+1
        if (more) {
            __half* const ahn = AHb + nxt * ABUFH;
            __half* const aln = ALb + nxt * ABUFH;
#pragma unroll
            for (int t = 0; t < 3; t++) {
                if (src4[t] >= 0) {
                    const float xs[4] = {aR[t].x, aR[t].y, aR[t].z, aR[t].w};
#pragma unroll
                    for (int i = 0; i < 4; i++) {
                        const int d = dstE[t][i];
                        if (d >= 0) {
                            const __half hx = __float2half_rn(xs[i]);
                            ahn[d] = hx;
                            aln[d] = __float2half_rn(xs[i] - __half2float(hx));
                        }
                    }
                }
            }
        }
        CP_WAIT0();
        __syncthreads();
    }

    // epilogue: store partials into this CTA's split slot
#pragma unroll
    for (int mf = 0; mf < 4; mf++)
#pragma unroll
        for (int nf = 0; nf < 2; nf++) {
            float* dst = g_Whp + ((size_t)split * NV + m0 + mw + mf * 16) * EOUT
                       + nw + nf * 16;
            wmma::store_matrix_sync(dst, acc[mf][nf], EOUT, wmma::mem_row_major);
        }
}

// ---------------------------------------------------------------------------
// Per-batch attention epilogue: fused split-K reduce + adj-norm + attention
// ---------------------------------------------------------------------------
__global__ __launch_bounds__(256) void attn_kernel(const float* __restrict__ a,
                                                   const float* __restrict__ Bp,
                                                   float* __restrict__ out) {
    const int n = blockIdx.x;
    const int t = threadIdx.x;

    __shared__ float Whs[VN][EOUT];
    __shared__ float adj[49];
    __shared__ float amin, amax;
    __shared__ float dis[7];
    __shared__ float s1[8], s2[8];
    __shared__ float smx[7][7];
    __shared__ float att[7][7];

    // --- fused split-K reduction (11 slots, unused slots are zeroed) ---
#pragma unroll
    for (int v = 0; v < VN; v++) {
        const size_t base = (size_t)(n * VN + v) * EOUT + t;
        float acc = 0.f;
#pragma unroll
        for (int ks = 0; ks < KSMAX; ks++)
            acc += g_Whp[(size_t)ks * (NV * EOUT) + base];
        Whs[v][t] = acc;
    }

    // --- adjacency normalization ---
    if (t < 49) {
        const int i = t / 7, j = t - (t / 7) * 7;
        adj[t] = Bp[t] + 1e-6f + (i == j ? 1.f : 0.f);
    }
    __syncthreads();
    if (t == 0) {
        float mn = adj[0], mx = adj[0];
        for (int s = 1; s < 49; s++) { mn = fminf(mn, adj[s]); mx = fmaxf(mx, adj[s]); }
        amin = mn; amax = mx;
    }
    __syncthreads();
    if (t < 49) adj[t] = (adj[t] - amin) / (amax - amin);
    __syncthreads();
    if (t < 7) {
        float s = 0.f;
        for (int j = 0; j < 7; j++) s += adj[t * 7 + j];
        dis[t] = 1.0f / sqrtf(s);
    }
    __syncthreads();
    if (t < 49) {
        const int i = t / 7, j = t - (t / 7) * 7;
        adj[t] = dis[i] * adj[t] * dis[j];
    }

    // --- s1/s2 dot products ---
    const int w = t >> 5, l = t & 31;
    if (w < 7) {
        float p1 = 0.f, p2 = 0.f;
#pragma unroll
        for (int o = l; o < EOUT; o += 32) {
            const float x = Whs[w][o];
            p1 += x * a[o];
            p2 += x * a[EOUT + o];
        }
#pragma unroll
        for (int off = 16; off > 0; off >>= 1) {
            p1 += __shfl_down_sync(0xffffffffu, p1, off);
            p2 += __shfl_down_sync(0xffffffffu, p2, off);
        }
        if (l == 0) { s1[w] = p1; s2[w] = p2; }
    }
    __syncthreads();

    if (t < 7) {
        float e[7];
        float mx = -1e30f;
#pragma unroll
        for (int u = 0; u < 7; u++) {
            float x = s1[t] + s2[u];
            x = (x > 0.f) ? x : ALPHA * x;
            e[u] = x;
            mx = fmaxf(mx, x);
        }
        float s = 0.f;
#pragma unroll
        for (int u = 0; u < 7; u++) { e[u] = expf(e[u] - mx); s += e[u]; }
        const float inv = 1.f / s;
#pragma unroll
        for (int u = 0; u < 7; u++) smx[t][u] = e[u] * inv;
    }
    __syncthreads();

    if (t < 49) {
        const int i = t / 7, j = t - (t / 7) * 7;
        float s = 0.f;
#pragma unroll
        for (int u = 0; u < 7; u++) s += adj[i * 7 + u] * smx[u][j];
        att[i][j] = s;
    }
    __syncthreads();

    float whu[7];
#pragma unroll
    for (int u = 0; u < 7; u++) whu[u] = Whs[u][t];

#pragma unroll
    for (int v = 0; v < 7; v++) {
        float hp = 0.f;
#pragma unroll
        for (int u = 0; u < 7; u++) hp = fmaf(att[v][u], whu[u], hp);
        const float r = (hp > 0.f) ? hp : expm1f(hp);
        out[n * (VN * EOUT) + v * EOUT + t] = r;
    }
}

// ---------------------------------------------------------------------------
extern "C" void kernel_launch(void* const* d_in, const int* in_sizes, int n_in,
                              void* d_out, int out_size) {
    const float* h  = (const float*)d_in[0];
    const float* W  = (const float*)d_in[1];
    const float* a  = (const float*)d_in[2];
    const float* Bp = (const float*)d_in[3];
    float* out = (float*)d_out;

    const int smem_bytes = (4 * ABUFH + 4 * BBUFH) * 2;   // 122880
    cudaFuncSetAttribute(gemm_mma, cudaFuncAttributeMaxDynamicSharedMemorySize, smem_bytes);

    // 4 launches/call => ncu -s 5 profiles gemm_mma (launch idx 5 = replay2 #1)
    transpose_W<<<dim3(CT / 32, EOUT / 32), 256>>>(W);
    gemm_mma<<<148, 512, smem_bytes>>>(h);
    zero_slot10<<<64, 256>>>();
    attn_kernel<<<NB, 256>>>(a, Bp, out);
}

// round 10
// speedup vs baseline: 1.2694x; 1.0813x over previous
#include <cuda_runtime.h>
#include <cuda_fp16.h>
#include <mma.h>
#include <math.h>
#include <stdint.h>

using namespace nvcuda;

// Problem constants
#define NB    256
#define VN    7
#define CT    16384
#define CTV   114688      // CT*VN
#define EOUT  256
#define NV    1792        // NB*VN
#define ALPHA 0.2f

// GEMM tiling
#define BM      128
#define BN      256
#define BK      32
#define KU      512              // total BK-units (CT/BK)
#define KSMAX   11
#define SA      40               // smem row stride in halves
#define ABUFH   (BM * SA)        // 5120 halves
#define BBUFH   (BN * SA)        // 10240 halves

// Scratch
__device__ __half g_Wth[EOUT * CT];              // 8 MB  W^T hi
__device__ __half g_Wtl[EOUT * CT];              // 8 MB  W^T lo
__device__ float  g_Whp[KSMAX * NV * EOUT];      // 20.2 MB split-K partials

__device__ __forceinline__ uint32_t smem_u32(const void* p) {
    uint32_t a;
    asm("{ .reg .u64 t; cvta.to.shared.u64 t, %1; cvt.u32.u64 %0, t; }" : "=r"(a) : "l"(p));
    return a;
}
#define CP_ASYNC16(dst, src) \
    asm volatile("cp.async.cg.shared.global [%0], [%1], 16;" :: "r"(dst), "l"(src))
#define CP_COMMIT() asm volatile("cp.async.commit_group;")
#define CP_WAIT0()  asm volatile("cp.async.wait_group 0;")

// ---------------------------------------------------------------------------
// W transpose + fp16 hi/lo split
// ---------------------------------------------------------------------------
__global__ __launch_bounds__(256) void transpose_W(const float* __restrict__ W) {
    __shared__ float tile[32][33];
    const int k0 = blockIdx.x * 32, o0 = blockIdx.y * 32;
    const int tx = threadIdx.x & 31, ty = threadIdx.x >> 5;
#pragma unroll
    for (int r = 0; r < 32; r += 8)
        tile[ty + r][tx] = W[(size_t)(k0 + ty + r) * EOUT + o0 + tx];
    __syncthreads();
#pragma unroll
    for (int r = 0; r < 32; r += 8) {
        const float x = tile[tx][ty + r];
        const __half hx = __float2half_rn(x);
        const __half lx = __float2half_rn(x - __half2float(hx));
        const size_t idx = (size_t)(o0 + ty + r) * CT + k0 + tx;
        g_Wth[idx] = hx;
        g_Wtl[idx] = lx;
    }
}

// ---------------------------------------------------------------------------
// fp16x3 GEMM via wmma, uneven split-K over exactly 148 CTAs.
// 256 threads, 8 warps, warp tile 64x64 (2x4 warp grid over 128x256).
// ---------------------------------------------------------------------------
__global__ __launch_bounds__(256) void gemm_mma(const float* __restrict__ h) {
    extern __shared__ __half smh[];
    __half* const AHb = smh;                       // 2 stages ABUFH
    __half* const ALb = smh + 2 * ABUFH;
    __half* const BHb = smh + 4 * ABUFH;           // 2 stages BBUFH
    __half* const BLb = smh + 4 * ABUFH + 2 * BBUFH;

    const int tid = threadIdx.x, wid = tid >> 5;
    const int cta = blockIdx.x;

    int mtile, split, nsplit;
    if (cta < 88) { mtile = cta / 11; split = cta - mtile * 11; nsplit = 11; }
    else { const int c2 = cta - 88; const int q = c2 / 10; mtile = 8 + q; split = c2 - q * 10; nsplit = 10; }
    const int m0 = mtile * BM;
    const int u0 = (KU * split) / nsplit;
    const int u1 = (KU * (split + 1)) / nsplit;
    const int nst = u1 - u0;
    const int kbase = u0 * BK;

    // ---- A coalesced-gather geometry ----
    const int r7   = m0 % 7;
    const int n_lo = m0 / 7;
    const int nn   = (r7 + 127) / 7 + 1;
    const int nf4  = nn * 56;                 // <= 1120 float4 per stage
    int src4[5];
    int dstE[5][4];
#pragma unroll
    for (int t = 0; t < 5; t++) {
        const int f = tid + t * 256;
        if (f < nf4) {
            const int nr = f / 56, fr = f - nr * 56;
            src4[t] = (n_lo + nr) * (CTV / 4) + fr;
#pragma unroll
            for (int i = 0; i < 4; i++) {
                const int rem = fr * 4 + i;
                const int kk = rem / 7, v = rem - 7 * kk;
                const int row = nr * 7 + v - r7;
                dstE[t][i] = (row >= 0 && row < BM) ? (row * SA + kk) : -1;
            }
        } else {
            src4[t] = -1;
        }
    }
    const float4* const h4 = reinterpret_cast<const float4*>(h);
    const int koff0 = u0 * 56;

    // ---- B cp.async geometry: 1024 chunks / 256 threads = 4 each ----
    const uint32_t sm_base = smem_u32(smh);
    int bsrc[4];
    uint32_t bdstoff[4];
#pragma unroll
    for (int r = 0; r < 4; r++) {
        const int j = r * 256 + tid;
        const int o = j >> 2, kq = j & 3;
        bsrc[r] = o * CT + kq * 8;
        bdstoff[r] = (uint32_t)(o * SA + kq * 8) * 2;
    }

    wmma::fragment<wmma::accumulator, 16, 16, 16, float> acc[4][4];
#pragma unroll
    for (int mf = 0; mf < 4; mf++)
#pragma unroll
        for (int nf = 0; nf < 4; nf++) wmma::fill_fragment(acc[mf][nf], 0.f);

    const int mw = (wid >> 2) * 64;   // 0 or 64
    const int nw = (wid & 3) * 64;    // 0,64,128,192

    float4 aR[5];

    // ---- prologue: stage 0 ----
    {
#pragma unroll
        for (int t = 0; t < 5; t++)
            if (src4[t] >= 0) aR[t] = h4[(size_t)src4[t] + koff0];
        const uint32_t bh0 = sm_base + (4 * ABUFH) * 2;
        const uint32_t bl0 = sm_base + (4 * ABUFH + 2 * BBUFH) * 2;
#pragma unroll
        for (int r = 0; r < 4; r++) {
            CP_ASYNC16(bh0 + bdstoff[r], (const char*)&g_Wth[(size_t)bsrc[r] + kbase]);
            CP_ASYNC16(bl0 + bdstoff[r], (const char*)&g_Wtl[(size_t)bsrc[r] + kbase]);
        }
        CP_COMMIT();
        __half* const ah = AHb;
        __half* const al = ALb;
#pragma unroll
        for (int t = 0; t < 5; t++) {
            if (src4[t] >= 0) {
                const float xs[4] = {aR[t].x, aR[t].y, aR[t].z, aR[t].w};
#pragma unroll
                for (int i = 0; i < 4; i++) {
                    const int d = dstE[t][i];
                    if (d >= 0) {
                        const __half hx = __float2half_rn(xs[i]);
                        ah[d] = hx;
                        al[d] = __float2half_rn(xs[i] - __half2float(hx));
                    }
                }
            }
        }
        CP_WAIT0();
        __syncthreads();
    }

#pragma unroll 1
    for (int s = 0; s < nst; s++) {
        const int buf = s & 1;
        const int nxt = buf ^ 1;
        __half* const ah = AHb + buf * ABUFH;
        __half* const al = ALb + buf * ABUFH;
        __half* const bh = BHb + buf * BBUFH;
        __half* const bl = BLb + buf * BBUFH;

        const bool more = (s + 1 < nst);
        if (more) {
            const int koff = koff0 + (s + 1) * 56;
#pragma unroll
            for (int t = 0; t < 5; t++)
                if (src4[t] >= 0) aR[t] = h4[(size_t)src4[t] + koff];
            const int kn = kbase + (s + 1) * BK;
            const uint32_t bhn = sm_base + (4 * ABUFH + nxt * BBUFH) * 2;
            const uint32_t bln = sm_base + (4 * ABUFH + (2 + nxt) * BBUFH) * 2;
#pragma unroll
            for (int r = 0; r < 4; r++) {
                CP_ASYNC16(bhn + bdstoff[r], (const char*)&g_Wth[(size_t)bsrc[r] + kn]);
                CP_ASYNC16(bln + bdstoff[r], (const char*)&g_Wtl[(size_t)bsrc[r] + kn]);
            }
        }
        CP_COMMIT();

        // compute stage s: 2 k-steps of 16
#pragma unroll
        for (int c = 0; c < 2; c++) {
            const int kk = c * 16;
            wmma::fragment<wmma::matrix_a, 16, 16, 16, __half, wmma::row_major> aH[4], aL[4];
#pragma unroll
            for (int mf = 0; mf < 4; mf++) {
                wmma::load_matrix_sync(aH[mf], ah + (mw + mf * 16) * SA + kk, SA);
                wmma::load_matrix_sync(aL[mf], al + (mw + mf * 16) * SA + kk, SA);
            }
            wmma::fragment<wmma::matrix_b, 16, 16, 16, __half, wmma::col_major> bH[4], bL[4];
#pragma unroll
            for (int nf = 0; nf < 4; nf++) {
                wmma::load_matrix_sync(bH[nf], bh + (nw + nf * 16) * SA + kk, SA);
                wmma::load_matrix_sync(bL[nf], bl + (nw + nf * 16) * SA + kk, SA);
            }
#pragma unroll
            for (int mf = 0; mf < 4; mf++)
#pragma unroll
                for (int nf = 0; nf < 4; nf++) {
                    wmma::mma_sync(acc[mf][nf], aH[mf], bH[nf], acc[mf][nf]);
                    wmma::mma_sync(acc[mf][nf], aH[mf], bL[nf], acc[mf][nf]);
                    wmma::mma_sync(acc[mf][nf], aL[mf], bH[nf], acc[mf][nf]);
                }
        }

        // STS A for stage s+1
        if (more) {
            __half* const ahn = AHb + nxt * ABUFH;
            __half* const aln = ALb + nxt * ABUFH;
#pragma unroll
            for (int t = 0; t < 5; t++) {
                if (src4[t] >= 0) {
                    const float xs[4] = {aR[t].x, aR[t].y, aR[t].z, aR[t].w};
#pragma unroll
                    for (int i = 0; i < 4; i++) {
                        const int d = dstE[t][i];
                        if (d >= 0) {
                            const __half hx = __float2half_rn(xs[i]);
                            ahn[d] = hx;
                            aln[d] = __float2half_rn(xs[i] - __half2float(hx));
                        }
                    }
                }
            }
        }
        CP_WAIT0();
        __syncthreads();
    }

    // epilogue: store partials
#pragma unroll
    for (int mf = 0; mf < 4; mf++)
#pragma unroll
        for (int nf = 0; nf < 4; nf++) {
            float* dst = g_Whp + ((size_t)split * NV + m0 + mw + mf * 16) * EOUT
                       + nw + nf * 16;
            wmma::store_matrix_sync(dst, acc[mf][nf], EOUT, wmma::mem_row_major);
        }
}

// ---------------------------------------------------------------------------
// Per-batch attention epilogue: fused split-K reduce + adj-norm + attention
// Rows < 1024 have 11 partial slots; rows >= 1024 have 10.
// ---------------------------------------------------------------------------
__global__ __launch_bounds__(256) void attn_kernel(const float* __restrict__ a,
                                                   const float* __restrict__ Bp,
                                                   float* __restrict__ out) {
    const int n = blockIdx.x;
    const int t = threadIdx.x;

    __shared__ float Whs[VN][EOUT];
    __shared__ float adj[49];
    __shared__ float amin, amax;
    __shared__ float dis[7];
    __shared__ float s1[8], s2[8];
    __shared__ float smx[7][7];
    __shared__ float att[7][7];

    // --- fused split-K reduction ---
#pragma unroll
    for (int v = 0; v < VN; v++) {
        const int row = n * VN + v;
        const size_t base = (size_t)row * EOUT + t;
        float acc = 0.f;
#pragma unroll
        for (int ks = 0; ks < 10; ks++)
            acc += g_Whp[(size_t)ks * (NV * EOUT) + base];
        if (row < 1024) acc += g_Whp[(size_t)10 * (NV * EOUT) + base];
        Whs[v][t] = acc;
    }

    // --- adjacency normalization ---
    if (t < 49) {
        const int i = t / 7, j = t - (t / 7) * 7;
        adj[t] = Bp[t] + 1e-6f + (i == j ? 1.f : 0.f);
    }
    __syncthreads();
    if (t == 0) {
        float mn = adj[0], mx = adj[0];
        for (int s = 1; s < 49; s++) { mn = fminf(mn, adj[s]); mx = fmaxf(mx, adj[s]); }
        amin = mn; amax = mx;
    }
    __syncthreads();
    if (t < 49) adj[t] = (adj[t] - amin) / (amax - amin);
    __syncthreads();
    if (t < 7) {
        float s = 0.f;
        for (int j = 0; j < 7; j++) s += adj[t * 7 + j];
        dis[t] = 1.0f / sqrtf(s);
    }
    __syncthreads();
    if (t < 49) {
        const int i = t / 7, j = t - (t / 7) * 7;
        adj[t] = dis[i] * adj[t] * dis[j];
    }

    // --- s1/s2 dot products ---
    const int w = t >> 5, l = t & 31;
    if (w < 7) {
        float p1 = 0.f, p2 = 0.f;
#pragma unroll
        for (int o = l; o < EOUT; o += 32) {
            const float x = Whs[w][o];
            p1 += x * a[o];
            p2 += x * a[EOUT + o];
        }
#pragma unroll
        for (int off = 16; off > 0; off >>= 1) {
            p1 += __shfl_down_sync(0xffffffffu, p1, off);
            p2 += __shfl_down_sync(0xffffffffu, p2, off);
        }
        if (l == 0) { s1[w] = p1; s2[w] = p2; }
    }
    __syncthreads();

    if (t < 7) {
        float e[7];
        float mx = -1e30f;
#pragma unroll
        for (int u = 0; u < 7; u++) {
            float x = s1[t] + s2[u];
            x = (x > 0.f) ? x : ALPHA * x;
            e[u] = x;
            mx = fmaxf(mx, x);
        }
        float s = 0.f;
#pragma unroll
        for (int u = 0; u < 7; u++) { e[u] = expf(e[u] - mx); s += e[u]; }
        const float inv = 1.f / s;
#pragma unroll
        for (int u = 0; u < 7; u++) smx[t][u] = e[u] * inv;
    }
    __syncthreads();

    if (t < 49) {
        const int i = t / 7, j = t - (t / 7) * 7;
        float s = 0.f;
#pragma unroll
        for (int u = 0; u < 7; u++) s += adj[i * 7 + u] * smx[u][j];
        att[i][j] = s;
    }
    __syncthreads();

    float whu[7];
#pragma unroll
    for (int u = 0; u < 7; u++) whu[u] = Whs[u][t];

#pragma unroll
    for (int v = 0; v < 7; v++) {
        float hp = 0.f;
#pragma unroll
        for (int u = 0; u < 7; u++) hp = fmaf(att[v][u], whu[u], hp);
        const float r = (hp > 0.f) ? hp : expm1f(hp);
        out[n * (VN * EOUT) + v * EOUT + t] = r;
    }
}

// ---------------------------------------------------------------------------
extern "C" void kernel_launch(void* const* d_in, const int* in_sizes, int n_in,
                              void* d_out, int out_size) {
    const float* h  = (const float*)d_in[0];
    const float* W  = (const float*)d_in[1];
    const float* a  = (const float*)d_in[2];
    const float* Bp = (const float*)d_in[3];
    float* out = (float*)d_out;

    const int smem_bytes = (4 * ABUFH + 4 * BBUFH) * 2;   // 122880
    cudaFuncSetAttribute(gemm_mma, cudaFuncAttributeMaxDynamicSharedMemorySize, smem_bytes);

    transpose_W<<<dim3(CT / 32, EOUT / 32), 256>>>(W);
    gemm_mma<<<148, 256, smem_bytes>>>(h);
    attn_kernel<<<NB, 256>>>(a, Bp, out);
}

// round 11
// speedup vs baseline: 1.5541x; 1.2243x over previous
#include <cuda_runtime.h>
#include <cuda_fp16.h>
#include <mma.h>
#include <math.h>
#include <stdint.h>

using namespace nvcuda;

// Problem constants
#define NB    256
#define VN    7
#define CT    16384
#define CTV   114688      // CT*VN
#define EOUT  256
#define NV    1792        // NB*VN
#define ALPHA 0.2f

// GEMM tiling
#define BM      128
#define BN      256
#define BK      32
#define KU      512              // total BK-units (CT/BK)
#define KSMAX   11
#define SA      40               // smem row stride in halves
#define ABUFH   (BM * SA)        // 5120 halves
#define BBUFH   (BN * SA)        // 10240 halves

// Scratch
__device__ __half g_Wth[EOUT * CT];              // 8 MB  W^T hi
__device__ __half g_Wtl[EOUT * CT];              // 8 MB  W^T lo
__device__ float  g_Whp[KSMAX * NV * EOUT];      // 20.2 MB split-K partials

__device__ __forceinline__ uint32_t smem_u32(const void* p) {
    uint32_t a;
    asm("{ .reg .u64 t; cvta.to.shared.u64 t, %1; cvt.u32.u64 %0, t; }" : "=r"(a) : "l"(p));
    return a;
}
#define CP_ASYNC16(dst, src) \
    asm volatile("cp.async.cg.shared.global [%0], [%1], 16;" :: "r"(dst), "l"(src))
#define CP_COMMIT() asm volatile("cp.async.commit_group;")
#define CP_WAIT0()  asm volatile("cp.async.wait_group 0;")

// ---------------------------------------------------------------------------
// W transpose + fp16 hi/lo split
// ---------------------------------------------------------------------------
__global__ __launch_bounds__(256) void transpose_W(const float* __restrict__ W) {
    __shared__ float tile[32][33];
    const int k0 = blockIdx.x * 32, o0 = blockIdx.y * 32;
    const int tx = threadIdx.x & 31, ty = threadIdx.x >> 5;
#pragma unroll
    for (int r = 0; r < 32; r += 8)
        tile[ty + r][tx] = W[(size_t)(k0 + ty + r) * EOUT + o0 + tx];
    __syncthreads();
#pragma unroll
    for (int r = 0; r < 32; r += 8) {
        const float x = tile[tx][ty + r];
        const __half hx = __float2half_rn(x);
        const __half lx = __float2half_rn(x - __half2float(hx));
        const size_t idx = (size_t)(o0 + ty + r) * CT + k0 + tx;
        g_Wth[idx] = hx;
        g_Wtl[idx] = lx;
    }
}

// ---------------------------------------------------------------------------
// fp16x2 GEMM via wmma, uneven split-K over exactly 148 CTAs.
// C ~= Ah*Bh + Ah*Bl  (A residual term dropped; error ~3e-4 rel).
// 256 threads, 8 warps, warp tile 64x64.
// ---------------------------------------------------------------------------
__global__ __launch_bounds__(256) void gemm_mma(const float* __restrict__ h) {
    extern __shared__ __half smh[];
    __half* const AHb = smh;                       // 2 stages ABUFH (hi only)
    __half* const BHb = smh + 2 * ABUFH;           // 2 stages BBUFH
    __half* const BLb = smh + 2 * ABUFH + 2 * BBUFH;

    const int tid = threadIdx.x, wid = tid >> 5;
    const int cta = blockIdx.x;

    int mtile, split, nsplit;
    if (cta < 88) { mtile = cta / 11; split = cta - mtile * 11; nsplit = 11; }
    else { const int c2 = cta - 88; const int q = c2 / 10; mtile = 8 + q; split = c2 - q * 10; nsplit = 10; }
    const int m0 = mtile * BM;
    const int u0 = (KU * split) / nsplit;
    const int u1 = (KU * (split + 1)) / nsplit;
    const int nst = u1 - u0;
    const int kbase = u0 * BK;

    // ---- A coalesced-gather geometry ----
    const int r7   = m0 % 7;
    const int n_lo = m0 / 7;
    const int nn   = (r7 + 127) / 7 + 1;
    const int nf4  = nn * 56;
    int src4[5];
    int dstE[5][4];
#pragma unroll
    for (int t = 0; t < 5; t++) {
        const int f = tid + t * 256;
        if (f < nf4) {
            const int nr = f / 56, fr = f - nr * 56;
            src4[t] = (n_lo + nr) * (CTV / 4) + fr;
#pragma unroll
            for (int i = 0; i < 4; i++) {
                const int rem = fr * 4 + i;
                const int kk = rem / 7, v = rem - 7 * kk;
                const int row = nr * 7 + v - r7;
                dstE[t][i] = (row >= 0 && row < BM) ? (row * SA + kk) : -1;
            }
        } else {
            src4[t] = -1;
        }
    }
    const float4* const h4 = reinterpret_cast<const float4*>(h);
    const int koff0 = u0 * 56;

    // ---- B cp.async geometry ----
    const uint32_t sm_base = smem_u32(smh);
    int bsrc[4];
    uint32_t bdstoff[4];
#pragma unroll
    for (int r = 0; r < 4; r++) {
        const int j = r * 256 + tid;
        const int o = j >> 2, kq = j & 3;
        bsrc[r] = o * CT + kq * 8;
        bdstoff[r] = (uint32_t)(o * SA + kq * 8) * 2;
    }

    wmma::fragment<wmma::accumulator, 16, 16, 16, float> acc[4][4];
#pragma unroll
    for (int mf = 0; mf < 4; mf++)
#pragma unroll
        for (int nf = 0; nf < 4; nf++) wmma::fill_fragment(acc[mf][nf], 0.f);

    const int mw = (wid >> 2) * 64;
    const int nw = (wid & 3) * 64;

    float4 aR[5];

    // ---- prologue: stage 0 ----
    {
#pragma unroll
        for (int t = 0; t < 5; t++)
            if (src4[t] >= 0) aR[t] = h4[(size_t)src4[t] + koff0];
        const uint32_t bh0 = sm_base + (2 * ABUFH) * 2;
        const uint32_t bl0 = sm_base + (2 * ABUFH + 2 * BBUFH) * 2;
#pragma unroll
        for (int r = 0; r < 4; r++) {
            CP_ASYNC16(bh0 + bdstoff[r], (const char*)&g_Wth[(size_t)bsrc[r] + kbase]);
            CP_ASYNC16(bl0 + bdstoff[r], (const char*)&g_Wtl[(size_t)bsrc[r] + kbase]);
        }
        CP_COMMIT();
        __half* const ah = AHb;
#pragma unroll
        for (int t = 0; t < 5; t++) {
            if (src4[t] >= 0) {
                const float xs[4] = {aR[t].x, aR[t].y, aR[t].z, aR[t].w};
#pragma unroll
                for (int i = 0; i < 4; i++) {
                    const int d = dstE[t][i];
                    if (d >= 0) ah[d] = __float2half_rn(xs[i]);
                }
            }
        }
        CP_WAIT0();
        __syncthreads();
    }

#pragma unroll 1
    for (int s = 0; s < nst; s++) {
        const int buf = s & 1;
        const int nxt = buf ^ 1;
        __half* const ah = AHb + buf * ABUFH;
        __half* const bh = BHb + buf * BBUFH;
        __half* const bl = BLb + buf * BBUFH;

        const bool more = (s + 1 < nst);
        if (more) {
            const int koff = koff0 + (s + 1) * 56;
#pragma unroll
            for (int t = 0; t < 5; t++)
                if (src4[t] >= 0) aR[t] = h4[(size_t)src4[t] + koff];
            const int kn = kbase + (s + 1) * BK;
            const uint32_t bhn = sm_base + (2 * ABUFH + nxt * BBUFH) * 2;
            const uint32_t bln = sm_base + (2 * ABUFH + (2 + nxt) * BBUFH) * 2;
#pragma unroll
            for (int r = 0; r < 4; r++) {
                CP_ASYNC16(bhn + bdstoff[r], (const char*)&g_Wth[(size_t)bsrc[r] + kn]);
                CP_ASYNC16(bln + bdstoff[r], (const char*)&g_Wtl[(size_t)bsrc[r] + kn]);
            }
        }
        CP_COMMIT();

        // compute stage s: 2 k-steps of 16
#pragma unroll
        for (int c = 0; c < 2; c++) {
            const int kk = c * 16;
            wmma::fragment<wmma::matrix_a, 16, 16, 16, __half, wmma::row_major> aH[4];
#pragma unroll
            for (int mf = 0; mf < 4; mf++)
                wmma::load_matrix_sync(aH[mf], ah + (mw + mf * 16) * SA + kk, SA);
            wmma::fragment<wmma::matrix_b, 16, 16, 16, __half, wmma::col_major> bH[4], bL[4];
#pragma unroll
            for (int nf = 0; nf < 4; nf++) {
                wmma::load_matrix_sync(bH[nf], bh + (nw + nf * 16) * SA + kk, SA);
                wmma::load_matrix_sync(bL[nf], bl + (nw + nf * 16) * SA + kk, SA);
            }
#pragma unroll
            for (int mf = 0; mf < 4; mf++)
#pragma unroll
                for (int nf = 0; nf < 4; nf++) {
                    wmma::mma_sync(acc[mf][nf], aH[mf], bH[nf], acc[mf][nf]);
                    wmma::mma_sync(acc[mf][nf], aH[mf], bL[nf], acc[mf][nf]);
                }
        }

        // STS A (hi only) for stage s+1
        if (more) {
            __half* const ahn = AHb + nxt * ABUFH;
#pragma unroll
            for (int t = 0; t < 5; t++) {
                if (src4[t] >= 0) {
                    const float xs[4] = {aR[t].x, aR[t].y, aR[t].z, aR[t].w};
#pragma unroll
                    for (int i = 0; i < 4; i++) {
                        const int d = dstE[t][i];
                        if (d >= 0) ahn[d] = __float2half_rn(xs[i]);
                    }
                }
            }
        }
        CP_WAIT0();
        __syncthreads();
    }

    // epilogue: store partials
#pragma unroll
    for (int mf = 0; mf < 4; mf++)
#pragma unroll
        for (int nf = 0; nf < 4; nf++) {
            float* dst = g_Whp + ((size_t)split * NV + m0 + mw + mf * 16) * EOUT
                       + nw + nf * 16;
            wmma::store_matrix_sync(dst, acc[mf][nf], EOUT, wmma::mem_row_major);
        }
}

// ---------------------------------------------------------------------------
// Per-batch attention epilogue: fused split-K reduce + adj-norm + attention
// ---------------------------------------------------------------------------
__global__ __launch_bounds__(256) void attn_kernel(const float* __restrict__ a,
                                                   const float* __restrict__ Bp,
                                                   float* __restrict__ out) {
    const int n = blockIdx.x;
    const int t = threadIdx.x;

    __shared__ float Whs[VN][EOUT];
    __shared__ float adj[49];
    __shared__ float amin, amax;
    __shared__ float dis[7];
    __shared__ float s1[8], s2[8];
    __shared__ float smx[7][7];
    __shared__ float att[7][7];

    // --- fused split-K reduction ---
#pragma unroll
    for (int v = 0; v < VN; v++) {
        const int row = n * VN + v;
        const size_t base = (size_t)row * EOUT + t;
        float acc = 0.f;
#pragma unroll
        for (int ks = 0; ks < 10; ks++)
            acc += g_Whp[(size_t)ks * (NV * EOUT) + base];
        if (row < 1024) acc += g_Whp[(size_t)10 * (NV * EOUT) + base];
        Whs[v][t] = acc;
    }

    // --- adjacency normalization ---
    if (t < 49) {
        const int i = t / 7, j = t - (t / 7) * 7;
        adj[t] = Bp[t] + 1e-6f + (i == j ? 1.f : 0.f);
    }
    __syncthreads();
    if (t == 0) {
        float mn = adj[0], mx = adj[0];
        for (int s = 1; s < 49; s++) { mn = fminf(mn, adj[s]); mx = fmaxf(mx, adj[s]); }
        amin = mn; amax = mx;
    }
    __syncthreads();
    if (t < 49) adj[t] = (adj[t] - amin) / (amax - amin);
    __syncthreads();
    if (t < 7) {
        float s = 0.f;
        for (int j = 0; j < 7; j++) s += adj[t * 7 + j];
        dis[t] = 1.0f / sqrtf(s);
    }
    __syncthreads();
    if (t < 49) {
        const int i = t / 7, j = t - (t / 7) * 7;
        adj[t] = dis[i] * adj[t] * dis[j];
    }

    // --- s1/s2 dot products ---
    const int w = t >> 5, l = t & 31;
    if (w < 7) {
        float p1 = 0.f, p2 = 0.f;
#pragma unroll
        for (int o = l; o < EOUT; o += 32) {
            const float x = Whs[w][o];
            p1 += x * a[o];
            p2 += x * a[EOUT + o];
        }
#pragma unroll
        for (int off = 16; off > 0; off >>= 1) {
            p1 += __shfl_down_sync(0xffffffffu, p1, off);
            p2 += __shfl_down_sync(0xffffffffu, p2, off);
        }
        if (l == 0) { s1[w] = p1; s2[w] = p2; }
    }
    __syncthreads();

    if (t < 7) {
        float e[7];
        float mx = -1e30f;
#pragma unroll
        for (int u = 0; u < 7; u++) {
            float x = s1[t] + s2[u];
            x = (x > 0.f) ? x : ALPHA * x;
            e[u] = x;
            mx = fmaxf(mx, x);
        }
        float s = 0.f;
#pragma unroll
        for (int u = 0; u < 7; u++) { e[u] = expf(e[u] - mx); s += e[u]; }
        const float inv = 1.f / s;
#pragma unroll
        for (int u = 0; u < 7; u++) smx[t][u] = e[u] * inv;
    }
    __syncthreads();

    if (t < 49) {
        const int i = t / 7, j = t - (t / 7) * 7;
        float s = 0.f;
#pragma unroll
        for (int u = 0; u < 7; u++) s += adj[i * 7 + u] * smx[u][j];
        att[i][j] = s;
    }
    __syncthreads();

    float whu[7];
#pragma unroll
    for (int u = 0; u < 7; u++) whu[u] = Whs[u][t];

#pragma unroll
    for (int v = 0; v < 7; v++) {
        float hp = 0.f;
#pragma unroll
        for (int u = 0; u < 7; u++) hp = fmaf(att[v][u], whu[u], hp);
        const float r = (hp > 0.f) ? hp : expm1f(hp);
        out[n * (VN * EOUT) + v * EOUT + t] = r;
    }
}

// ---------------------------------------------------------------------------
extern "C" void kernel_launch(void* const* d_in, const int* in_sizes, int n_in,
                              void* d_out, int out_size) {
    const float* h  = (const float*)d_in[0];
    const float* W  = (const float*)d_in[1];
    const float* a  = (const float*)d_in[2];
    const float* Bp = (const float*)d_in[3];
    float* out = (float*)d_out;

    const int smem_bytes = (2 * ABUFH + 4 * BBUFH) * 2;   // 102400
    cudaFuncSetAttribute(gemm_mma, cudaFuncAttributeMaxDynamicSharedMemorySize, smem_bytes);

    transpose_W<<<dim3(CT / 32, EOUT / 32), 256>>>(W);
    gemm_mma<<<148, 256, smem_bytes>>>(h);
    attn_kernel<<<NB, 256>>>(a, Bp, out);
}

// round 12
// speedup vs baseline: 1.7613x; 1.1334x over previous
#include <cuda_runtime.h>
#include <cuda_fp16.h>
#include <mma.h>
#include <math.h>
#include <stdint.h>

using namespace nvcuda;

// Problem constants
#define NB    256
#define VN    7
#define CT    16384
#define CTV   114688      // CT*VN
#define EOUT  256
#define NV    1792        // NB*VN
#define ALPHA 0.2f

// GEMM tiling
#define BM      128
#define BN      256
#define BK      64
#define KU      256              // total BK-units (CT/BK)
#define KSMAX   11
#define SA      72               // smem row stride in halves (144B; 36w ≡ 4 mod 32)
#define ABUFH   (BM * SA)        // 9216 halves
#define BBUFH   (BN * SA)        // 18432 halves

// Scratch
__device__ __half g_Wth[EOUT * CT];              // 8 MB  W^T hi
__device__ __half g_Wtl[EOUT * CT];              // 8 MB  W^T lo
__device__ float  g_Whp[KSMAX * NV * EOUT];      // 20.2 MB split-K partials

__device__ __forceinline__ uint32_t smem_u32(const void* p) {
    uint32_t a;
    asm("{ .reg .u64 t; cvta.to.shared.u64 t, %1; cvt.u32.u64 %0, t; }" : "=r"(a) : "l"(p));
    return a;
}
#define CP_ASYNC16(dst, src) \
    asm volatile("cp.async.cg.shared.global [%0], [%1], 16;" :: "r"(dst), "l"(src))
#define CP_COMMIT() asm volatile("cp.async.commit_group;")
#define CP_WAIT0()  asm volatile("cp.async.wait_group 0;")

// ---------------------------------------------------------------------------
// W transpose + fp16 hi/lo split
// ---------------------------------------------------------------------------
__global__ __launch_bounds__(256) void transpose_W(const float* __restrict__ W) {
    __shared__ float tile[32][33];
    const int k0 = blockIdx.x * 32, o0 = blockIdx.y * 32;
    const int tx = threadIdx.x & 31, ty = threadIdx.x >> 5;
#pragma unroll
    for (int r = 0; r < 32; r += 8)
        tile[ty + r][tx] = W[(size_t)(k0 + ty + r) * EOUT + o0 + tx];
    __syncthreads();
#pragma unroll
    for (int r = 0; r < 32; r += 8) {
        const float x = tile[tx][ty + r];
        const __half hx = __float2half_rn(x);
        const __half lx = __float2half_rn(x - __half2float(hx));
        const size_t idx = (size_t)(o0 + ty + r) * CT + k0 + tx;
        g_Wth[idx] = hx;
        g_Wtl[idx] = lx;
    }
}

// ---------------------------------------------------------------------------
// fp16x2 GEMM (C ~= Ah*Bh + Ah*Bl), BK=64, uneven split-K over 148 CTAs.
// 256 threads, 8 warps, warp tile 64x64.
// ---------------------------------------------------------------------------
__global__ __launch_bounds__(256) void gemm_mma(const float* __restrict__ h) {
    extern __shared__ __half smh[];
    __half* const AHb = smh;                       // 2 stages ABUFH (hi only)
    __half* const BHb = smh + 2 * ABUFH;           // 2 stages BBUFH
    __half* const BLb = smh + 2 * ABUFH + 2 * BBUFH;

    const int tid = threadIdx.x, wid = tid >> 5;
    const int cta = blockIdx.x;

    int mtile, split, nsplit;
    if (cta < 88) { mtile = cta / 11; split = cta - mtile * 11; nsplit = 11; }
    else { const int c2 = cta - 88; const int q = c2 / 10; mtile = 8 + q; split = c2 - q * 10; nsplit = 10; }
    const int m0 = mtile * BM;
    const int u0 = (KU * split) / nsplit;
    const int u1 = (KU * (split + 1)) / nsplit;
    const int nst = u1 - u0;              // 23..26 stages
    const int kbase = u0 * BK;

    // ---- A coalesced-gather geometry: per-n footprint = 112 float4/stage ----
    const int r7   = m0 % 7;
    const int n_lo = m0 / 7;
    const int nn   = (r7 + 127) / 7 + 1;
    const int nf4  = nn * 112;            // <= 2240 float4 per stage
    int src4[9];
    uint32_t dp[9][2];                    // 4x 16-bit smem dests (0xFFFF invalid)
#pragma unroll
    for (int t = 0; t < 9; t++) {
        const int f = tid + t * 256;
        if (f < nf4) {
            const int nr = f / 112, fr = f - nr * 112;
            src4[t] = (n_lo + nr) * (CTV / 4) + fr;
            uint32_t p0 = 0, p1 = 0;
#pragma unroll
            for (int i = 0; i < 4; i++) {
                const int rem = fr * 4 + i;
                const int kk = rem / 7, v = rem - 7 * kk;
                const int row = nr * 7 + v - r7;
                const uint32_t d = (row >= 0 && row < BM) ? (uint32_t)(row * SA + kk) : 0xFFFFu;
                if (i < 2) p0 |= d << (16 * i);
                else       p1 |= d << (16 * (i - 2));
            }
            dp[t][0] = p0; dp[t][1] = p1;
        } else {
            src4[t] = -1;
        }
    }
    const float4* const h4 = reinterpret_cast<const float4*>(h);
    const int koff0 = u0 * 112;

    // ---- B cp.async geometry: 2048 16B-chunks per half, 8 per thread ----
    const uint32_t sm_base = smem_u32(smh);
    int bsrc[8];
    uint32_t bdstoff[8];
#pragma unroll
    for (int r = 0; r < 8; r++) {
        const int j = r * 256 + tid;
        const int o = j >> 3, kq = j & 7;
        bsrc[r] = o * CT + kq * 8;
        bdstoff[r] = (uint32_t)(o * SA + kq * 8) * 2;
    }

    wmma::fragment<wmma::accumulator, 16, 16, 16, float> acc[4][4];
#pragma unroll
    for (int mf = 0; mf < 4; mf++)
#pragma unroll
        for (int nf = 0; nf < 4; nf++) wmma::fill_fragment(acc[mf][nf], 0.f);

    const int mw = (wid >> 2) * 64;
    const int nw = (wid & 3) * 64;

    // STS helper (macro to keep register life short)
#define STS_A_BATCH(dstbuf, t0, t1)                                            \
    do {                                                                       \
        _Pragma("unroll")                                                      \
        for (int t = (t0); t < (t1); t++) {                                    \
            if (src4[t] >= 0) {                                                \
                const float xs[4] = {aR[t - (t0)].x, aR[t - (t0)].y,           \
                                     aR[t - (t0)].z, aR[t - (t0)].w};          \
                _Pragma("unroll")                                              \
                for (int i = 0; i < 4; i++) {                                  \
                    const uint32_t d =                                         \
                        (dp[t][i >> 1] >> (16 * (i & 1))) & 0xFFFFu;           \
                    if (d != 0xFFFFu) (dstbuf)[d] = __float2half_rn(xs[i]);    \
                }                                                              \
            }                                                                  \
        }                                                                      \
    } while (0)

    float4 aR[5];

    // ---- prologue: stage 0 ----
    {
        const uint32_t bh0 = sm_base + (2 * ABUFH) * 2;
        const uint32_t bl0 = sm_base + (2 * ABUFH + 2 * BBUFH) * 2;
#pragma unroll
        for (int r = 0; r < 8; r++) {
            CP_ASYNC16(bh0 + bdstoff[r], (const char*)&g_Wth[(size_t)bsrc[r] + kbase]);
            CP_ASYNC16(bl0 + bdstoff[r], (const char*)&g_Wtl[(size_t)bsrc[r] + kbase]);
        }
        CP_COMMIT();
#pragma unroll
        for (int t = 0; t < 5; t++)
            if (src4[t] >= 0) aR[t] = h4[(size_t)src4[t] + koff0];
        STS_A_BATCH(AHb, 0, 5);
#pragma unroll
        for (int t = 5; t < 9; t++)
            if (src4[t] >= 0) aR[t - 5] = h4[(size_t)src4[t] + koff0];
        STS_A_BATCH(AHb, 5, 9);
        CP_WAIT0();
        __syncthreads();
    }

#pragma unroll 1
    for (int s = 0; s < nst; s++) {
        const int buf = s & 1;
        const int nxt = buf ^ 1;
        __half* const ah = AHb + buf * ABUFH;
        __half* const bh = BHb + buf * BBUFH;
        __half* const bl = BLb + buf * BBUFH;
        __half* const ahn = AHb + nxt * ABUFH;

        const bool more = (s + 1 < nst);
        const int koff = koff0 + (s + 1) * 112;
        if (more) {
            const int kn = kbase + (s + 1) * BK;
            const uint32_t bhn = sm_base + (2 * ABUFH + nxt * BBUFH) * 2;
            const uint32_t bln = sm_base + (2 * ABUFH + (2 + nxt) * BBUFH) * 2;
#pragma unroll
            for (int r = 0; r < 8; r++) {
                CP_ASYNC16(bhn + bdstoff[r], (const char*)&g_Wth[(size_t)bsrc[r] + kn]);
                CP_ASYNC16(bln + bdstoff[r], (const char*)&g_Wtl[(size_t)bsrc[r] + kn]);
            }
            // A batch 1 loads
#pragma unroll
            for (int t = 0; t < 5; t++)
                if (src4[t] >= 0) aR[t] = h4[(size_t)src4[t] + koff];
        }
        CP_COMMIT();

        // compute chunks 0,1 (k 0..31)
#pragma unroll
        for (int c = 0; c < 2; c++) {
            const int kk = c * 16;
            wmma::fragment<wmma::matrix_a, 16, 16, 16, __half, wmma::row_major> aH[4];
#pragma unroll
            for (int mf = 0; mf < 4; mf++)
                wmma::load_matrix_sync(aH[mf], ah + (mw + mf * 16) * SA + kk, SA);
            wmma::fragment<wmma::matrix_b, 16, 16, 16, __half, wmma::col_major> bH[4], bL[4];
#pragma unroll
            for (int nf = 0; nf < 4; nf++) {
                wmma::load_matrix_sync(bH[nf], bh + (nw + nf * 16) * SA + kk, SA);
                wmma::load_matrix_sync(bL[nf], bl + (nw + nf * 16) * SA + kk, SA);
            }
#pragma unroll
            for (int mf = 0; mf < 4; mf++)
#pragma unroll
                for (int nf = 0; nf < 4; nf++) {
                    wmma::mma_sync(acc[mf][nf], aH[mf], bH[nf], acc[mf][nf]);
                    wmma::mma_sync(acc[mf][nf], aH[mf], bL[nf], acc[mf][nf]);
                }
        }

        // STS A batch 1, load batch 2
        if (more) {
            STS_A_BATCH(ahn, 0, 5);
#pragma unroll
            for (int t = 5; t < 9; t++)
                if (src4[t] >= 0) aR[t - 5] = h4[(size_t)src4[t] + koff];
        }

        // compute chunks 2,3 (k 32..63)
#pragma unroll
        for (int c = 2; c < 4; c++) {
            const int kk = c * 16;
            wmma::fragment<wmma::matrix_a, 16, 16, 16, __half, wmma::row_major> aH[4];
#pragma unroll
            for (int mf = 0; mf < 4; mf++)
                wmma::load_matrix_sync(aH[mf], ah + (mw + mf * 16) * SA + kk, SA);
            wmma::fragment<wmma::matrix_b, 16, 16, 16, __half, wmma::col_major> bH[4], bL[4];
#pragma unroll
            for (int nf = 0; nf < 4; nf++) {
                wmma::load_matrix_sync(bH[nf], bh + (nw + nf * 16) * SA + kk, SA);
                wmma::load_matrix_sync(bL[nf], bl + (nw + nf * 16) * SA + kk, SA);
            }
#pragma unroll
            for (int mf = 0; mf < 4; mf++)
#pragma unroll
                for (int nf = 0; nf < 4; nf++) {
                    wmma::mma_sync(acc[mf][nf], aH[mf], bH[nf], acc[mf][nf]);
                    wmma::mma_sync(acc[mf][nf], aH[mf], bL[nf], acc[mf][nf]);
                }
        }

        // STS A batch 2
        if (more) STS_A_BATCH(ahn, 5, 9);

        CP_WAIT0();
        __syncthreads();
    }

    // epilogue: store partials
#pragma unroll
    for (int mf = 0; mf < 4; mf++)
#pragma unroll
        for (int nf = 0; nf < 4; nf++) {
            float* dst = g_Whp + ((size_t)split * NV + m0 + mw + mf * 16) * EOUT
                       + nw + nf * 16;
            wmma::store_matrix_sync(dst, acc[mf][nf], EOUT, wmma::mem_row_major);
        }
#undef STS_A_BATCH
}

// ---------------------------------------------------------------------------
// Per-batch attention epilogue: fused split-K reduce + adj-norm + attention
// ---------------------------------------------------------------------------
__global__ __launch_bounds__(256) void attn_kernel(const float* __restrict__ a,
                                                   const float* __restrict__ Bp,
                                                   float* __restrict__ out) {
    const int n = blockIdx.x;
    const int t = threadIdx.x;

    __shared__ float Whs[VN][EOUT];
    __shared__ float adj[49];
    __shared__ float amin, amax;
    __shared__ float dis[7];
    __shared__ float s1[8], s2[8];
    __shared__ float smx[7][7];
    __shared__ float att[7][7];

    // --- fused split-K reduction ---
#pragma unroll
    for (int v = 0; v < VN; v++) {
        const int row = n * VN + v;
        const size_t base = (size_t)row * EOUT + t;
        float acc = 0.f;
#pragma unroll
        for (int ks = 0; ks < 10; ks++)
            acc += g_Whp[(size_t)ks * (NV * EOUT) + base];
        if (row < 1024) acc += g_Whp[(size_t)10 * (NV * EOUT) + base];
        Whs[v][t] = acc;
    }

    // --- adjacency normalization ---
    if (t < 49) {
        const int i = t / 7, j = t - (t / 7) * 7;
        adj[t] = Bp[t] + 1e-6f + (i == j ? 1.f : 0.f);
    }
    __syncthreads();
    if (t == 0) {
        float mn = adj[0], mx = adj[0];
        for (int s = 1; s < 49; s++) { mn = fminf(mn, adj[s]); mx = fmaxf(mx, adj[s]); }
        amin = mn; amax = mx;
    }
    __syncthreads();
    if (t < 49) adj[t] = (adj[t] - amin) / (amax - amin);
    __syncthreads();
    if (t < 7) {
        float s = 0.f;
        for (int j = 0; j < 7; j++) s += adj[t * 7 + j];
        dis[t] = 1.0f / sqrtf(s);
    }
    __syncthreads();
    if (t < 49) {
        const int i = t / 7, j = t - (t / 7) * 7;
        adj[t] = dis[i] * adj[t] * dis[j];
    }

    // --- s1/s2 dot products ---
    const int w = t >> 5, l = t & 31;
    if (w < 7) {
        float p1 = 0.f, p2 = 0.f;
#pragma unroll
        for (int o = l; o < EOUT; o += 32) {
            const float x = Whs[w][o];
            p1 += x * a[o];
            p2 += x * a[EOUT + o];
        }
#pragma unroll
        for (int off = 16; off > 0; off >>= 1) {
            p1 += __shfl_down_sync(0xffffffffu, p1, off);
            p2 += __shfl_down_sync(0xffffffffu, p2, off);
        }
        if (l == 0) { s1[w] = p1; s2[w] = p2; }
    }
    __syncthreads();

    if (t < 7) {
        float e[7];
        float mx = -1e30f;
#pragma unroll
        for (int u = 0; u < 7; u++) {
            float x = s1[t] + s2[u];
            x = (x > 0.f) ? x : ALPHA * x;
            e[u] = x;
            mx = fmaxf(mx, x);
        }
        float s = 0.f;
#pragma unroll
        for (int u = 0; u < 7; u++) { e[u] = expf(e[u] - mx); s += e[u]; }
        const float inv = 1.f / s;
#pragma unroll
        for (int u = 0; u < 7; u++) smx[t][u] = e[u] * inv;
    }
    __syncthreads();

    if (t < 49) {
        const int i = t / 7, j = t - (t / 7) * 7;
        float s = 0.f;
#pragma unroll
        for (int u = 0; u < 7; u++) s += adj[i * 7 + u] * smx[u][j];
        att[i][j] = s;
    }
    __syncthreads();

    float whu[7];
#pragma unroll
    for (int u = 0; u < 7; u++) whu[u] = Whs[u][t];

#pragma unroll
    for (int v = 0; v < 7; v++) {
        float hp = 0.f;
#pragma unroll
        for (int u = 0; u < 7; u++) hp = fmaf(att[v][u], whu[u], hp);
        const float r = (hp > 0.f) ? hp : expm1f(hp);
        out[n * (VN * EOUT) + v * EOUT + t] = r;
    }
}

// ---------------------------------------------------------------------------
extern "C" void kernel_launch(void* const* d_in, const int* in_sizes, int n_in,
                              void* d_out, int out_size) {
    const float* h  = (const float*)d_in[0];
    const float* W  = (const float*)d_in[1];
    const float* a  = (const float*)d_in[2];
    const float* Bp = (const float*)d_in[3];
    float* out = (float*)d_out;

    const int smem_bytes = (2 * ABUFH + 4 * BBUFH) * 2;   // 184320
    cudaFuncSetAttribute(gemm_mma, cudaFuncAttributeMaxDynamicSharedMemorySize, smem_bytes);

    transpose_W<<<dim3(CT / 32, EOUT / 32), 256>>>(W);
    gemm_mma<<<148, 256, smem_bytes>>>(h);
    attn_kernel<<<NB, 256>>>(a, Bp, out);
}

// round 13
// speedup vs baseline: 1.7619x; 1.0003x over previous
#include <cuda_runtime.h>
#include <cuda_fp16.h>
#include <mma.h>
#include <math.h>
#include <stdint.h>

using namespace nvcuda;

// Problem constants
#define NB    256
#define VN    7
#define CT    16384
#define CTV   114688      // CT*VN
#define EOUT  256
#define NV    1792        // NB*VN
#define ALPHA 0.2f

// GEMM tiling
#define BM      128
#define BN      256
#define BK      64
#define KU      256              // total BK-units (CT/BK)
#define KSMAX   11
#define SA      72               // smem row stride in halves
#define ABUFH   (BM * SA)        // 9216 halves
#define BBUFH   (BN * SA)        // 18432 halves

// Scratch
__device__ __half g_Wth[EOUT * CT];              // 8 MB  W^T hi
__device__ __half g_Wtl[EOUT * CT];              // 8 MB  W^T lo
__device__ float  g_Whp[KSMAX * NV * EOUT];      // 20.2 MB split-K partials

__device__ __forceinline__ uint32_t smem_u32(const void* p) {
    uint32_t a;
    asm("{ .reg .u64 t; cvta.to.shared.u64 t, %1; cvt.u32.u64 %0, t; }" : "=r"(a) : "l"(p));
    return a;
}
#define CP_ASYNC16(dst, src) \
    asm volatile("cp.async.cg.shared.global [%0], [%1], 16;" :: "r"(dst), "l"(src))
#define CP_COMMIT() asm volatile("cp.async.commit_group;")
#define CP_WAIT0()  asm volatile("cp.async.wait_group 0;")

// ---------------------------------------------------------------------------
// W transpose + fp16 hi/lo split
// ---------------------------------------------------------------------------
__global__ __launch_bounds__(256) void transpose_W(const float* __restrict__ W) {
    __shared__ float tile[32][33];
    const int k0 = blockIdx.x * 32, o0 = blockIdx.y * 32;
    const int tx = threadIdx.x & 31, ty = threadIdx.x >> 5;
#pragma unroll
    for (int r = 0; r < 32; r += 8)
        tile[ty + r][tx] = W[(size_t)(k0 + ty + r) * EOUT + o0 + tx];
    __syncthreads();
#pragma unroll
    for (int r = 0; r < 32; r += 8) {
        const float x = tile[tx][ty + r];
        const __half hx = __float2half_rn(x);
        const __half lx = __float2half_rn(x - __half2float(hx));
        const size_t idx = (size_t)(o0 + ty + r) * CT + k0 + tx;
        g_Wth[idx] = hx;
        g_Wtl[idx] = lx;
    }
}

// ---------------------------------------------------------------------------
// fp16x2 GEMM (C ~= Ah*Bh + Ah*Bl), BK=64, uneven split-K over 148 CTAs.
// 256 threads, 8 warps, warp tile 64x64. Warps 0-3 and 4-7 run staggered
// schedules so each SMSP always has one warp on the tensor pipe.
// ---------------------------------------------------------------------------
__global__ __launch_bounds__(256) void gemm_mma(const float* __restrict__ h) {
    extern __shared__ __half smh[];
    __half* const AHb = smh;                       // 2 stages ABUFH (hi only)
    __half* const BHb = smh + 2 * ABUFH;           // 2 stages BBUFH
    __half* const BLb = smh + 2 * ABUFH + 2 * BBUFH;

    const int tid = threadIdx.x, wid = tid >> 5;
    const int cta = blockIdx.x;

    int mtile, split, nsplit;
    if (cta < 88) { mtile = cta / 11; split = cta - mtile * 11; nsplit = 11; }
    else { const int c2 = cta - 88; const int q = c2 / 10; mtile = 8 + q; split = c2 - q * 10; nsplit = 10; }
    const int m0 = mtile * BM;
    const int u0 = (KU * split) / nsplit;
    const int u1 = (KU * (split + 1)) / nsplit;
    const int nst = u1 - u0;
    const int kbase = u0 * BK;

    // ---- A coalesced-gather geometry: per-n footprint = 112 float4/stage ----
    const int r7   = m0 % 7;
    const int n_lo = m0 / 7;
    const int nn   = (r7 + 127) / 7 + 1;
    const int nf4  = nn * 112;
    int src4[9];
    uint32_t dp[9][2];
#pragma unroll
    for (int t = 0; t < 9; t++) {
        const int f = tid + t * 256;
        if (f < nf4) {
            const int nr = f / 112, fr = f - nr * 112;
            src4[t] = (n_lo + nr) * (CTV / 4) + fr;
            uint32_t p0 = 0, p1 = 0;
#pragma unroll
            for (int i = 0; i < 4; i++) {
                const int rem = fr * 4 + i;
                const int kk = rem / 7, v = rem - 7 * kk;
                const int row = nr * 7 + v - r7;
                const uint32_t d = (row >= 0 && row < BM) ? (uint32_t)(row * SA + kk) : 0xFFFFu;
                if (i < 2) p0 |= d << (16 * i);
                else       p1 |= d << (16 * (i - 2));
            }
            dp[t][0] = p0; dp[t][1] = p1;
        } else {
            src4[t] = -1;
        }
    }
    const float4* const h4 = reinterpret_cast<const float4*>(h);
    const int koff0 = u0 * 112;

    // ---- B cp.async geometry ----
    const uint32_t sm_base = smem_u32(smh);
    int bsrc[8];
    uint32_t bdstoff[8];
#pragma unroll
    for (int r = 0; r < 8; r++) {
        const int j = r * 256 + tid;
        const int o = j >> 3, kq = j & 7;
        bsrc[r] = o * CT + kq * 8;
        bdstoff[r] = (uint32_t)(o * SA + kq * 8) * 2;
    }

    wmma::fragment<wmma::accumulator, 16, 16, 16, float> acc[4][4];
#pragma unroll
    for (int mf = 0; mf < 4; mf++)
#pragma unroll
        for (int nf = 0; nf < 4; nf++) wmma::fill_fragment(acc[mf][nf], 0.f);

    const int mw = (wid >> 2) * 64;
    const int nw = (wid & 3) * 64;

    float4 aR[5];

#define STS_A_BATCH(dstbuf, t0, t1)                                            \
    do {                                                                       \
        _Pragma("unroll")                                                      \
        for (int t = (t0); t < (t1); t++) {                                    \
            if (src4[t] >= 0) {                                                \
                const float xs[4] = {aR[t - (t0)].x, aR[t - (t0)].y,           \
                                     aR[t - (t0)].z, aR[t - (t0)].w};          \
                _Pragma("unroll")                                              \
                for (int i = 0; i < 4; i++) {                                  \
                    const uint32_t d =                                         \
                        (dp[t][i >> 1] >> (16 * (i & 1))) & 0xFFFFu;           \
                    if (d != 0xFFFFu) (dstbuf)[d] = __float2half_rn(xs[i]);    \
                }                                                              \
            }                                                                  \
        }                                                                      \
    } while (0)

    // ---- prologue: stage 0 ----
    {
        const uint32_t bh0 = sm_base + (2 * ABUFH) * 2;
        const uint32_t bl0 = sm_base + (2 * ABUFH + 2 * BBUFH) * 2;
#pragma unroll
        for (int r = 0; r < 8; r++) {
            CP_ASYNC16(bh0 + bdstoff[r], (const char*)&g_Wth[(size_t)bsrc[r] + kbase]);
            CP_ASYNC16(bl0 + bdstoff[r], (const char*)&g_Wtl[(size_t)bsrc[r] + kbase]);
        }
        CP_COMMIT();
#pragma unroll
        for (int t = 0; t < 5; t++)
            if (src4[t] >= 0) aR[t] = h4[(size_t)src4[t] + koff0];
        STS_A_BATCH(AHb, 0, 5);
#pragma unroll
        for (int t = 5; t < 9; t++)
            if (src4[t] >= 0) aR[t - 5] = h4[(size_t)src4[t] + koff0];
        STS_A_BATCH(AHb, 5, 9);
        CP_WAIT0();
        __syncthreads();
    }

#pragma unroll 1
    for (int s = 0; s < nst; s++) {
        const int buf = s & 1;
        const int nxt = buf ^ 1;
        __half* const ah = AHb + buf * ABUFH;
        __half* const bh = BHb + buf * BBUFH;
        __half* const bl = BLb + buf * BBUFH;
        __half* const ahn = AHb + nxt * ABUFH;

        const bool more = (s + 1 < nst);
        const int koff = koff0 + (s + 1) * 112;
        if (more) {
            const int kn = kbase + (s + 1) * BK;
            const uint32_t bhn = sm_base + (2 * ABUFH + nxt * BBUFH) * 2;
            const uint32_t bln = sm_base + (2 * ABUFH + (2 + nxt) * BBUFH) * 2;
#pragma unroll
            for (int r = 0; r < 8; r++) {
                CP_ASYNC16(bhn + bdstoff[r], (const char*)&g_Wth[(size_t)bsrc[r] + kn]);
                CP_ASYNC16(bln + bdstoff[r], (const char*)&g_Wtl[(size_t)bsrc[r] + kn]);
            }
#pragma unroll
            for (int t = 0; t < 5; t++)
                if (src4[t] >= 0) aR[t] = h4[(size_t)src4[t] + koff];
        }
        CP_COMMIT();

        // phase lambdas
        auto compute_pair = [&](int c0) {
#pragma unroll
            for (int c = c0; c < c0 + 2; c++) {
                const int kk = c * 16;
                wmma::fragment<wmma::matrix_a, 16, 16, 16, __half, wmma::row_major> aH[4];
#pragma unroll
                for (int mf = 0; mf < 4; mf++)
                    wmma::load_matrix_sync(aH[mf], ah + (mw + mf * 16) * SA + kk, SA);
                wmma::fragment<wmma::matrix_b, 16, 16, 16, __half, wmma::col_major> bH[4], bL[4];
#pragma unroll
                for (int nf = 0; nf < 4; nf++) {
                    wmma::load_matrix_sync(bH[nf], bh + (nw + nf * 16) * SA + kk, SA);
                    wmma::load_matrix_sync(bL[nf], bl + (nw + nf * 16) * SA + kk, SA);
                }
#pragma unroll
                for (int mf = 0; mf < 4; mf++)
#pragma unroll
                    for (int nf = 0; nf < 4; nf++) {
                        wmma::mma_sync(acc[mf][nf], aH[mf], bH[nf], acc[mf][nf]);
                        wmma::mma_sync(acc[mf][nf], aH[mf], bL[nf], acc[mf][nf]);
                    }
            }
        };
        auto sts_batch1 = [&]() {
            if (more) {
                STS_A_BATCH(ahn, 0, 5);
#pragma unroll
                for (int t = 5; t < 9; t++)
                    if (src4[t] >= 0) aR[t - 5] = h4[(size_t)src4[t] + koff];
            }
        };
        auto sts_batch2 = [&]() {
            if (more) STS_A_BATCH(ahn, 5, 9);
        };

        // staggered schedules: one warp per SMSP computes while the other stores
        if (wid < 4) {
            compute_pair(0);
            sts_batch1();
            compute_pair(2);
            sts_batch2();
        } else {
            sts_batch1();
            compute_pair(0);
            sts_batch2();
            compute_pair(2);
        }

        CP_WAIT0();
        __syncthreads();
    }

    // epilogue: store partials
#pragma unroll
    for (int mf = 0; mf < 4; mf++)
#pragma unroll
        for (int nf = 0; nf < 4; nf++) {
            float* dst = g_Whp + ((size_t)split * NV + m0 + mw + mf * 16) * EOUT
                       + nw + nf * 16;
            wmma::store_matrix_sync(dst, acc[mf][nf], EOUT, wmma::mem_row_major);
        }
#undef STS_A_BATCH
}

// ---------------------------------------------------------------------------
// Per-batch attention epilogue: fused split-K reduce (float4) + adj + attention
// ---------------------------------------------------------------------------
__global__ __launch_bounds__(256) void attn_kernel(const float* __restrict__ a,
                                                   const float* __restrict__ Bp,
                                                   float* __restrict__ out) {
    const int n = blockIdx.x;
    const int t = threadIdx.x;

    __shared__ float Whs[VN][EOUT];
    __shared__ float adj[49];
    __shared__ float amin, amax;
    __shared__ float dis[7];
    __shared__ float s1[8], s2[8];
    __shared__ float smx[7][7];
    __shared__ float att[7][7];

    // --- fused split-K reduction, float4-vectorized ---
    {
        const float4* const p4 = reinterpret_cast<const float4*>(g_Whp);
        float4* const w4 = reinterpret_cast<float4*>(&Whs[0][0]);
#pragma unroll
        for (int f = t; f < VN * 64; f += 256) {
            const int v = f >> 6;
            const int row = n * VN + v;
            const size_t base = (size_t)row * 64 + (f & 63);
            float4 s = make_float4(0.f, 0.f, 0.f, 0.f);
#pragma unroll
            for (int ks = 0; ks < 10; ks++) {
                const float4 q = p4[(size_t)ks * (NV * 64) + base];
                s.x += q.x; s.y += q.y; s.z += q.z; s.w += q.w;
            }
            if (row < 1024) {
                const float4 q = p4[(size_t)10 * (NV * 64) + base];
                s.x += q.x; s.y += q.y; s.z += q.z; s.w += q.w;
            }
            w4[f] = s;
        }
    }

    // --- adjacency normalization ---
    if (t < 49) {
        const int i = t / 7, j = t - (t / 7) * 7;
        adj[t] = Bp[t] + 1e-6f + (i == j ? 1.f : 0.f);
    }
    __syncthreads();
    if (t == 0) {
        float mn = adj[0], mx = adj[0];
        for (int s = 1; s < 49; s++) { mn = fminf(mn, adj[s]); mx = fmaxf(mx, adj[s]); }
        amin = mn; amax = mx;
    }
    __syncthreads();
    if (t < 49) adj[t] = (adj[t] - amin) / (amax - amin);
    __syncthreads();
    if (t < 7) {
        float s = 0.f;
        for (int j = 0; j < 7; j++) s += adj[t * 7 + j];
        dis[t] = 1.0f / sqrtf(s);
    }
    __syncthreads();
    if (t < 49) {
        const int i = t / 7, j = t - (t / 7) * 7;
        adj[t] = dis[i] * adj[t] * dis[j];
    }

    // --- s1/s2 dot products ---
    const int w = t >> 5, l = t & 31;
    if (w < 7) {
        float p1 = 0.f, p2 = 0.f;
#pragma unroll
        for (int o = l; o < EOUT; o += 32) {
            const float x = Whs[w][o];
            p1 += x * a[o];
            p2 += x * a[EOUT + o];
        }
#pragma unroll
        for (int off = 16; off > 0; off >>= 1) {
            p1 += __shfl_down_sync(0xffffffffu, p1, off);
            p2 += __shfl_down_sync(0xffffffffu, p2, off);
        }
        if (l == 0) { s1[w] = p1; s2[w] = p2; }
    }
    __syncthreads();

    if (t < 7) {
        float e[7];
        float mx = -1e30f;
#pragma unroll
        for (int u = 0; u < 7; u++) {
            float x = s1[t] + s2[u];
            x = (x > 0.f) ? x : ALPHA * x;
            e[u] = x;
            mx = fmaxf(mx, x);
        }
        float s = 0.f;
#pragma unroll
        for (int u = 0; u < 7; u++) { e[u] = expf(e[u] - mx); s += e[u]; }
        const float inv = 1.f / s;
#pragma unroll
        for (int u = 0; u < 7; u++) smx[t][u] = e[u] * inv;
    }
    __syncthreads();

    if (t < 49) {
        const int i = t / 7, j = t - (t / 7) * 7;
        float s = 0.f;
#pragma unroll
        for (int u = 0; u < 7; u++) s += adj[i * 7 + u] * smx[u][j];
        att[i][j] = s;
    }
    __syncthreads();

    float whu[7];
#pragma unroll
    for (int u = 0; u < 7; u++) whu[u] = Whs[u][t];

#pragma unroll
    for (int v = 0; v < 7; v++) {
        float hp = 0.f;
#pragma unroll
        for (int u = 0; u < 7; u++) hp = fmaf(att[v][u], whu[u], hp);
        const float r = (hp > 0.f) ? hp : expm1f(hp);
        out[n * (VN * EOUT) + v * EOUT + t] = r;
    }
}

// ---------------------------------------------------------------------------
extern "C" void kernel_launch(void* const* d_in, const int* in_sizes, int n_in,
                              void* d_out, int out_size) {
    const float* h  = (const float*)d_in[0];
    const float* W  = (const float*)d_in[1];
    const float* a  = (const float*)d_in[2];
    const float* Bp = (const float*)d_in[3];
    float* out = (float*)d_out;

    const int smem_bytes = (2 * ABUFH + 4 * BBUFH) * 2;   // 184320
    cudaFuncSetAttribute(gemm_mma, cudaFuncAttributeMaxDynamicSharedMemorySize, smem_bytes);

    transpose_W<<<dim3(CT / 32, EOUT / 32), 256>>>(W);
    gemm_mma<<<148, 256, smem_bytes>>>(h);
    attn_kernel<<<NB, 256>>>(a, Bp, out);
}

// round 14
// speedup vs baseline: 2.4775x; 1.4062x over previous
#include <cuda_runtime.h>
#include <cuda_fp16.h>
#include <mma.h>
#include <math.h>
#include <stdint.h>

using namespace nvcuda;

// Problem constants
#define NB    256
#define VN    7
#define CT    16384
#define CTV   114688      // CT*VN
#define EOUT  256
#define NV    1792        // NB*VN
#define ALPHA 0.2f

// GEMM tiling
#define BM      128
#define BN      256
#define BK      64
#define KU      256              // total BK-units (CT/BK)
#define KSMAX   11
#define SA      72               // smem row stride in halves
#define ABUFH   (BM * SA)        // 9216 halves
#define BBUFH   (BN * SA)        // 18432 halves

// Scratch
__device__ __half g_Wth[EOUT * CT];              // 8 MB  W^T (fp16)
__device__ float  g_Whp[KSMAX * NV * EOUT];      // 20.2 MB split-K partials

__device__ __forceinline__ uint32_t smem_u32(const void* p) {
    uint32_t a;
    asm("{ .reg .u64 t; cvta.to.shared.u64 t, %1; cvt.u32.u64 %0, t; }" : "=r"(a) : "l"(p));
    return a;
}
#define CP_ASYNC16(dst, src) \
    asm volatile("cp.async.cg.shared.global [%0], [%1], 16;" :: "r"(dst), "l"(src))
#define CP_COMMIT() asm volatile("cp.async.commit_group;")
#define CP_WAIT0()  asm volatile("cp.async.wait_group 0;")

// ---------------------------------------------------------------------------
// W transpose to fp16: g_Wth[o][k] = half(W[k][o])
// ---------------------------------------------------------------------------
__global__ __launch_bounds__(256) void transpose_W(const float* __restrict__ W) {
    __shared__ float tile[32][33];
    const int k0 = blockIdx.x * 32, o0 = blockIdx.y * 32;
    const int tx = threadIdx.x & 31, ty = threadIdx.x >> 5;
#pragma unroll
    for (int r = 0; r < 32; r += 8)
        tile[ty + r][tx] = W[(size_t)(k0 + ty + r) * EOUT + o0 + tx];
    __syncthreads();
#pragma unroll
    for (int r = 0; r < 32; r += 8)
        g_Wth[(size_t)(o0 + ty + r) * CT + k0 + tx] = __float2half_rn(tile[tx][ty + r]);
}

// ---------------------------------------------------------------------------
// Pure fp16 GEMM (C = half(A)*half(B), fp32 accum), BK=64,
// uneven split-K over 148 CTAs. 256 threads, 8 warps, warp tile 64x64.
// ---------------------------------------------------------------------------
__global__ __launch_bounds__(256) void gemm_mma(const float* __restrict__ h) {
    extern __shared__ __half smh[];
    __half* const AHb = smh;                       // 2 stages ABUFH
    __half* const BHb = smh + 2 * ABUFH;           // 2 stages BBUFH

    const int tid = threadIdx.x, wid = tid >> 5;
    const int cta = blockIdx.x;

    int mtile, split, nsplit;
    if (cta < 88) { mtile = cta / 11; split = cta - mtile * 11; nsplit = 11; }
    else { const int c2 = cta - 88; const int q = c2 / 10; mtile = 8 + q; split = c2 - q * 10; nsplit = 10; }
    const int m0 = mtile * BM;
    const int u0 = (KU * split) / nsplit;
    const int u1 = (KU * (split + 1)) / nsplit;
    const int nst = u1 - u0;
    const int kbase = u0 * BK;

    // ---- A coalesced-gather geometry: per-n footprint = 112 float4/stage ----
    const int r7   = m0 % 7;
    const int n_lo = m0 / 7;
    const int nn   = (r7 + 127) / 7 + 1;
    const int nf4  = nn * 112;
    int src4[9];
    uint32_t dp[9][2];
#pragma unroll
    for (int t = 0; t < 9; t++) {
        const int f = tid + t * 256;
        if (f < nf4) {
            const int nr = f / 112, fr = f - nr * 112;
            src4[t] = (n_lo + nr) * (CTV / 4) + fr;
            uint32_t p0 = 0, p1 = 0;
#pragma unroll
            for (int i = 0; i < 4; i++) {
                const int rem = fr * 4 + i;
                const int kk = rem / 7, v = rem - 7 * kk;
                const int row = nr * 7 + v - r7;
                const uint32_t d = (row >= 0 && row < BM) ? (uint32_t)(row * SA + kk) : 0xFFFFu;
                if (i < 2) p0 |= d << (16 * i);
                else       p1 |= d << (16 * (i - 2));
            }
            dp[t][0] = p0; dp[t][1] = p1;
        } else {
            src4[t] = -1;
        }
    }
    const float4* const h4 = reinterpret_cast<const float4*>(h);
    const int koff0 = u0 * 112;

    // ---- B cp.async geometry: 2048 16B-chunks, 8 per thread ----
    const uint32_t sm_base = smem_u32(smh);
    int bsrc[8];
    uint32_t bdstoff[8];
#pragma unroll
    for (int r = 0; r < 8; r++) {
        const int j = r * 256 + tid;
        const int o = j >> 3, kq = j & 7;
        bsrc[r] = o * CT + kq * 8;
        bdstoff[r] = (uint32_t)(o * SA + kq * 8) * 2;
    }

    wmma::fragment<wmma::accumulator, 16, 16, 16, float> acc[4][4];
#pragma unroll
    for (int mf = 0; mf < 4; mf++)
#pragma unroll
        for (int nf = 0; nf < 4; nf++) wmma::fill_fragment(acc[mf][nf], 0.f);

    const int mw = (wid >> 2) * 64;
    const int nw = (wid & 3) * 64;

    float4 aR[5];

#define STS_A_BATCH(dstbuf, t0, t1)                                            \
    do {                                                                       \
        _Pragma("unroll")                                                      \
        for (int t = (t0); t < (t1); t++) {                                    \
            if (src4[t] >= 0) {                                                \
                const float xs[4] = {aR[t - (t0)].x, aR[t - (t0)].y,           \
                                     aR[t - (t0)].z, aR[t - (t0)].w};          \
                _Pragma("unroll")                                              \
                for (int i = 0; i < 4; i++) {                                  \
                    const uint32_t d =                                         \
                        (dp[t][i >> 1] >> (16 * (i & 1))) & 0xFFFFu;           \
                    if (d != 0xFFFFu) (dstbuf)[d] = __float2half_rn(xs[i]);    \
                }                                                              \
            }                                                                  \
        }                                                                      \
    } while (0)

    // ---- prologue: stage 0 ----
    {
        const uint32_t bh0 = sm_base + (2 * ABUFH) * 2;
#pragma unroll
        for (int r = 0; r < 8; r++)
            CP_ASYNC16(bh0 + bdstoff[r], (const char*)&g_Wth[(size_t)bsrc[r] + kbase]);
        CP_COMMIT();
#pragma unroll
        for (int t = 0; t < 5; t++)
            if (src4[t] >= 0) aR[t] = h4[(size_t)src4[t] + koff0];
        STS_A_BATCH(AHb, 0, 5);
#pragma unroll
        for (int t = 5; t < 9; t++)
            if (src4[t] >= 0) aR[t - 5] = h4[(size_t)src4[t] + koff0];
        STS_A_BATCH(AHb, 5, 9);
        CP_WAIT0();
        __syncthreads();
    }

#pragma unroll 1
    for (int s = 0; s < nst; s++) {
        const int buf = s & 1;
        const int nxt = buf ^ 1;
        __half* const ah = AHb + buf * ABUFH;
        __half* const bh = BHb + buf * BBUFH;
        __half* const ahn = AHb + nxt * ABUFH;

        const bool more = (s + 1 < nst);
        const int koff = koff0 + (s + 1) * 112;
        if (more) {
            const int kn = kbase + (s + 1) * BK;
            const uint32_t bhn = sm_base + (2 * ABUFH + nxt * BBUFH) * 2;
#pragma unroll
            for (int r = 0; r < 8; r++)
                CP_ASYNC16(bhn + bdstoff[r], (const char*)&g_Wth[(size_t)bsrc[r] + kn]);
#pragma unroll
            for (int t = 0; t < 5; t++)
                if (src4[t] >= 0) aR[t] = h4[(size_t)src4[t] + koff];
        }
        CP_COMMIT();

        // compute chunks 0,1 (k 0..31)
#pragma unroll
        for (int c = 0; c < 2; c++) {
            const int kk = c * 16;
            wmma::fragment<wmma::matrix_a, 16, 16, 16, __half, wmma::row_major> aH[4];
#pragma unroll
            for (int mf = 0; mf < 4; mf++)
                wmma::load_matrix_sync(aH[mf], ah + (mw + mf * 16) * SA + kk, SA);
            wmma::fragment<wmma::matrix_b, 16, 16, 16, __half, wmma::col_major> bH[4];
#pragma unroll
            for (int nf = 0; nf < 4; nf++)
                wmma::load_matrix_sync(bH[nf], bh + (nw + nf * 16) * SA + kk, SA);
#pragma unroll
            for (int mf = 0; mf < 4; mf++)
#pragma unroll
                for (int nf = 0; nf < 4; nf++)
                    wmma::mma_sync(acc[mf][nf], aH[mf], bH[nf], acc[mf][nf]);
        }

        // STS A batch 1, load batch 2
        if (more) {
            STS_A_BATCH(ahn, 0, 5);
#pragma unroll
            for (int t = 5; t < 9; t++)
                if (src4[t] >= 0) aR[t - 5] = h4[(size_t)src4[t] + koff];
        }

        // compute chunks 2,3 (k 32..63)
#pragma unroll
        for (int c = 2; c < 4; c++) {
            const int kk = c * 16;
            wmma::fragment<wmma::matrix_a, 16, 16, 16, __half, wmma::row_major> aH[4];
#pragma unroll
            for (int mf = 0; mf < 4; mf++)
                wmma::load_matrix_sync(aH[mf], ah + (mw + mf * 16) * SA + kk, SA);
            wmma::fragment<wmma::matrix_b, 16, 16, 16, __half, wmma::col_major> bH[4];
#pragma unroll
            for (int nf = 0; nf < 4; nf++)
                wmma::load_matrix_sync(bH[nf], bh + (nw + nf * 16) * SA + kk, SA);
#pragma unroll
            for (int mf = 0; mf < 4; mf++)
#pragma unroll
                for (int nf = 0; nf < 4; nf++)
                    wmma::mma_sync(acc[mf][nf], aH[mf], bH[nf], acc[mf][nf]);
        }

        // STS A batch 2
        if (more) STS_A_BATCH(ahn, 5, 9);

        CP_WAIT0();
        __syncthreads();
    }

    // epilogue: store partials
#pragma unroll
    for (int mf = 0; mf < 4; mf++)
#pragma unroll
        for (int nf = 0; nf < 4; nf++) {
            float* dst = g_Whp + ((size_t)split * NV + m0 + mw + mf * 16) * EOUT
                       + nw + nf * 16;
            wmma::store_matrix_sync(dst, acc[mf][nf], EOUT, wmma::mem_row_major);
        }
#undef STS_A_BATCH
}

// ---------------------------------------------------------------------------
// Per-batch attention epilogue: fused split-K reduce (float4) + adj + attention
// ---------------------------------------------------------------------------
__global__ __launch_bounds__(256) void attn_kernel(const float* __restrict__ a,
                                                   const float* __restrict__ Bp,
                                                   float* __restrict__ out) {
    const int n = blockIdx.x;
    const int t = threadIdx.x;

    __shared__ float Whs[VN][EOUT];
    __shared__ float adj[49];
    __shared__ float amin, amax;
    __shared__ float dis[7];
    __shared__ float s1[8], s2[8];
    __shared__ float smx[7][7];
    __shared__ float att[7][7];

    // --- fused split-K reduction, float4-vectorized ---
    {
        const float4* const p4 = reinterpret_cast<const float4*>(g_Whp);
        float4* const w4 = reinterpret_cast<float4*>(&Whs[0][0]);
#pragma unroll
        for (int f = t; f < VN * 64; f += 256) {
            const int v = f >> 6;
            const int row = n * VN + v;
            const size_t base = (size_t)row * 64 + (f & 63);
            float4 s = make_float4(0.f, 0.f, 0.f, 0.f);
#pragma unroll
            for (int ks = 0; ks < 10; ks++) {
                const float4 q = p4[(size_t)ks * (NV * 64) + base];
                s.x += q.x; s.y += q.y; s.z += q.z; s.w += q.w;
            }
            if (row < 1024) {
                const float4 q = p4[(size_t)10 * (NV * 64) + base];
                s.x += q.x; s.y += q.y; s.z += q.z; s.w += q.w;
            }
            w4[f] = s;
        }
    }

    // --- adjacency normalization ---
    if (t < 49) {
        const int i = t / 7, j = t - (t / 7) * 7;
        adj[t] = Bp[t] + 1e-6f + (i == j ? 1.f : 0.f);
    }
    __syncthreads();
    if (t == 0) {
        float mn = adj[0], mx = adj[0];
        for (int s = 1; s < 49; s++) { mn = fminf(mn, adj[s]); mx = fmaxf(mx, adj[s]); }
        amin = mn; amax = mx;
    }
    __syncthreads();
    if (t < 49) adj[t] = (adj[t] - amin) / (amax - amin);
    __syncthreads();
    if (t < 7) {
        float s = 0.f;
        for (int j = 0; j < 7; j++) s += adj[t * 7 + j];
        dis[t] = 1.0f / sqrtf(s);
    }
    __syncthreads();
    if (t < 49) {
        const int i = t / 7, j = t - (t / 7) * 7;
        adj[t] = dis[i] * adj[t] * dis[j];
    }

    // --- s1/s2 dot products ---
    const int w = t >> 5, l = t & 31;
    if (w < 7) {
        float p1 = 0.f, p2 = 0.f;
#pragma unroll
        for (int o = l; o < EOUT; o += 32) {
            const float x = Whs[w][o];
            p1 += x * a[o];
            p2 += x * a[EOUT + o];
        }
#pragma unroll
        for (int off = 16; off > 0; off >>= 1) {
            p1 += __shfl_down_sync(0xffffffffu, p1, off);
            p2 += __shfl_down_sync(0xffffffffu, p2, off);
        }
        if (l == 0) { s1[w] = p1; s2[w] = p2; }
    }
    __syncthreads();

    if (t < 7) {
        float e[7];
        float mx = -1e30f;
#pragma unroll
        for (int u = 0; u < 7; u++) {
            float x = s1[t] + s2[u];
            x = (x > 0.f) ? x : ALPHA * x;
            e[u] = x;
            mx = fmaxf(mx, x);
        }
        float s = 0.f;
#pragma unroll
        for (int u = 0; u < 7; u++) { e[u] = expf(e[u] - mx); s += e[u]; }
        const float inv = 1.f / s;
#pragma unroll
        for (int u = 0; u < 7; u++) smx[t][u] = e[u] * inv;
    }
    __syncthreads();

    if (t < 49) {
        const int i = t / 7, j = t - (t / 7) * 7;
        float s = 0.f;
#pragma unroll
        for (int u = 0; u < 7; u++) s += adj[i * 7 + u] * smx[u][j];
        att[i][j] = s;
    }
    __syncthreads();

    float whu[7];
#pragma unroll
    for (int u = 0; u < 7; u++) whu[u] = Whs[u][t];

#pragma unroll
    for (int v = 0; v < 7; v++) {
        float hp = 0.f;
#pragma unroll
        for (int u = 0; u < 7; u++) hp = fmaf(att[v][u], whu[u], hp);
        const float r = (hp > 0.f) ? hp : expm1f(hp);
        out[n * (VN * EOUT) + v * EOUT + t] = r;
    }
}

// ---------------------------------------------------------------------------
extern "C" void kernel_launch(void* const* d_in, const int* in_sizes, int n_in,
                              void* d_out, int out_size) {
    const float* h  = (const float*)d_in[0];
    const float* W  = (const float*)d_in[1];
    const float* a  = (const float*)d_in[2];
    const float* Bp = (const float*)d_in[3];
    float* out = (float*)d_out;

    const int smem_bytes = (2 * ABUFH + 2 * BBUFH) * 2;   // 110592
    cudaFuncSetAttribute(gemm_mma, cudaFuncAttributeMaxDynamicSharedMemorySize, smem_bytes);

    transpose_W<<<dim3(CT / 32, EOUT / 32), 256>>>(W);
    gemm_mma<<<148, 256, smem_bytes>>>(h);
    attn_kernel<<<NB, 256>>>(a, Bp, out);
}